// round 1
// baseline (speedup 1.0000x reference)
#include <cuda_runtime.h>
#include <math_constants.h>

#define DIMK   2048
#define NBLK   2000
#define NROWS  32768        // 32 * 1024
#define T_PER_B 1024
#define NB_HALF 16

#define BM 128
#define BN 128
#define BK 32
#define TM 8
#define TN 8
#define NTHREADS 256

// ---------------- device scratch (static, allowed) ----------------
__device__ float        g_invx[NROWS];
__device__ float        g_invw[NBLK];
__device__ unsigned int g_rowmax[NROWS];   // order-preserving encoded float max
__device__ float        g_s[NB_HALF * NBLK];
__device__ float        g_div;

// order-preserving float<->uint encoding (for atomicMax over signed floats)
__device__ __forceinline__ unsigned int enc_f(float f) {
    unsigned int u = __float_as_uint(f);
    return (u & 0x80000000u) ? ~u : (u | 0x80000000u);
}
__device__ __forceinline__ float dec_f(unsigned int u) {
    unsigned int b = (u & 0x80000000u) ? (u ^ 0x80000000u) : ~u;
    return __uint_as_float(b);
}

// ---------------- init ----------------
__global__ void init_kernel() {
    int i = blockIdx.x * blockDim.x + threadIdx.x;
    if (i < NB_HALF * NBLK) g_s[i] = 0.0f;
    if (i < NROWS)          g_rowmax[i] = 0u;   // below enc(-inf)
    if (i == 0)             g_div = 0.0f;
}

// ---------------- per-row inverse L2 norm ----------------
__global__ void row_invnorm_kernel(const float* __restrict__ X, float* __restrict__ out) {
    int r = blockIdx.x;
    const float4* xp = (const float4*)(X + (size_t)r * DIMK);
    float ss = 0.0f;
    for (int i = threadIdx.x; i < DIMK / 4; i += blockDim.x) {
        float4 v = xp[i];
        ss += v.x * v.x + v.y * v.y + v.z * v.z + v.w * v.w;
    }
    __shared__ float sm[32];
    int lane = threadIdx.x & 31, wid = threadIdx.x >> 5;
    #pragma unroll
    for (int o = 16; o; o >>= 1) ss += __shfl_down_sync(0xffffffffu, ss, o);
    if (lane == 0) sm[wid] = ss;
    __syncthreads();
    if (wid == 0) {
        float v = (lane < (int)(blockDim.x >> 5)) ? sm[lane] : 0.0f;
        #pragma unroll
        for (int o = 16; o; o >>= 1) v += __shfl_down_sync(0xffffffffu, v, o);
        if (lane == 0) out[r] = 1.0f / fmaxf(sqrtf(v), 1e-12f);
    }
}

// ---------------- main fused GEMM: att = (X Wt) * invx * invw ----------------
// grid: (16 n-tiles, 256 row-tiles), 256 threads
__global__ __launch_bounds__(NTHREADS, 2)
void att_gemm_kernel(const float* __restrict__ X, const float* __restrict__ W,
                     const int* __restrict__ mask) {
    __shared__ float As[BK][BM];
    __shared__ float Bs[BK][BN];

    const int nt = blockIdx.x;
    const int rt = blockIdx.y;
    const int row0 = rt * BM;
    const int col0 = nt * BN;
    const int tid = threadIdx.x;
    const int tm = tid >> 4;
    const int tn = tid & 15;

    float acc[TM][TN];
    #pragma unroll
    for (int i = 0; i < TM; i++)
        #pragma unroll
        for (int j = 0; j < TN; j++) acc[i][j] = 0.0f;

    for (int k0 = 0; k0 < DIMK; k0 += BK) {
        #pragma unroll
        for (int i = 0; i < 4; i++) {
            int id = tid + i * NTHREADS;
            int r = id >> 3;
            int kq = id & 7;
            float4 v = *(const float4*)(X + (size_t)(row0 + r) * DIMK + k0 + kq * 4);
            As[kq * 4 + 0][r] = v.x;
            As[kq * 4 + 1][r] = v.y;
            As[kq * 4 + 2][r] = v.z;
            As[kq * 4 + 3][r] = v.w;
        }
        #pragma unroll
        for (int i = 0; i < 4; i++) {
            int id = tid + i * NTHREADS;
            int r = id >> 3;
            int kq = id & 7;
            int gc = col0 + r;
            float4 v = make_float4(0.f, 0.f, 0.f, 0.f);
            if (gc < NBLK) v = *(const float4*)(W + (size_t)gc * DIMK + k0 + kq * 4);
            Bs[kq * 4 + 0][r] = v.x;
            Bs[kq * 4 + 1][r] = v.y;
            Bs[kq * 4 + 2][r] = v.z;
            Bs[kq * 4 + 3][r] = v.w;
        }
        __syncthreads();
        #pragma unroll
        for (int k = 0; k < BK; k++) {
            float ra[TM], rb[TN];
            *(float4*)&ra[0] = *(const float4*)&As[k][tm * TM];
            *(float4*)&ra[4] = *(const float4*)&As[k][tm * TM + 4];
            *(float4*)&rb[0] = *(const float4*)&Bs[k][tn * TN];
            *(float4*)&rb[4] = *(const float4*)&Bs[k][tn * TN + 4];
            #pragma unroll
            for (int i = 0; i < TM; i++)
                #pragma unroll
                for (int j = 0; j < TN; j++) acc[i][j] += ra[i] * rb[j];
        }
        __syncthreads();
    }

    // ---- epilogue ----
    float invwj[TN];
    bool  validj[TN];
    #pragma unroll
    for (int j = 0; j < TN; j++) {
        int n = col0 + tn * TN + j;
        validj[j] = (n < NBLK);
        invwj[j] = validj[j] ? g_invw[n] : 0.0f;
    }

    // per-thread row maxima over its 8 columns (invw applied per column)
    float rmax[TM];
    #pragma unroll
    for (int i = 0; i < TM; i++) {
        float m = -CUDART_INF_F;
        #pragma unroll
        for (int j = 0; j < TN; j++)
            if (validj[j]) m = fmaxf(m, acc[i][j] * invwj[j]);
        rmax[i] = m;
    }

    const bool first_half = (rt < (NROWS / BM) / 2);  // rt < 128  <=> b < 16

    // masked column partial sums (first half only)
    float csum[TN];
    if (first_half) {
        float rowf[TM];
        #pragma unroll
        for (int i = 0; i < TM; i++) {
            int gr = row0 + tm * TM + i;
            rowf[i] = g_invx[gr] * (float)mask[gr];
        }
        #pragma unroll
        for (int j = 0; j < TN; j++) {
            float s = 0.0f;
            #pragma unroll
            for (int i = 0; i < TM; i++) s += acc[i][j] * rowf[i];
            csum[j] = s;
        }
    }

    // smem reductions: reuse As for rowmax red [16][128], Bs for colsum red [16][128]
    float (*redm)[BM] = (float(*)[BM])As;
    float (*redc)[BN] = (float(*)[BN])Bs;
    #pragma unroll
    for (int i = 0; i < TM; i++) redm[tn][tm * TM + i] = rmax[i];
    if (first_half) {
        #pragma unroll
        for (int j = 0; j < TN; j++) redc[tm][tn * TN + j] = csum[j];
    }
    __syncthreads();

    if (tid < BM) {
        float m = redm[0][tid];
        #pragma unroll
        for (int t = 1; t < 16; t++) m = fmaxf(m, redm[t][tid]);
        int gr = row0 + tid;
        m *= g_invx[gr];
        atomicMax(&g_rowmax[gr], enc_f(m));
    }
    if (first_half && tid < BN) {
        int n = col0 + tid;
        if (n < NBLK) {
            float s = 0.0f;
            #pragma unroll
            for (int t = 0; t < 16; t++) s += redc[t][tid];
            s *= g_invw[n];
            int b = rt >> 3;  // 8 row-tiles per batch
            atomicAdd(&g_s[b * NBLK + n], s);
        }
    }
}

// ---------------- diversity GEMM: accumulate ||W Wt - I||_F^2 ----------------
__global__ __launch_bounds__(NTHREADS, 2)
void div_gemm_kernel(const float* __restrict__ W) {
    __shared__ float As[BK][BM];
    __shared__ float Bs[BK][BN];

    const int nt = blockIdx.x;
    const int rt = blockIdx.y;
    const int row0 = rt * BM;
    const int col0 = nt * BN;
    const int tid = threadIdx.x;
    const int tm = tid >> 4;
    const int tn = tid & 15;

    float acc[TM][TN];
    #pragma unroll
    for (int i = 0; i < TM; i++)
        #pragma unroll
        for (int j = 0; j < TN; j++) acc[i][j] = 0.0f;

    for (int k0 = 0; k0 < DIMK; k0 += BK) {
        #pragma unroll
        for (int i = 0; i < 4; i++) {
            int id = tid + i * NTHREADS;
            int r = id >> 3;
            int kq = id & 7;
            int gr = row0 + r;
            float4 v = make_float4(0.f, 0.f, 0.f, 0.f);
            if (gr < NBLK) v = *(const float4*)(W + (size_t)gr * DIMK + k0 + kq * 4);
            As[kq * 4 + 0][r] = v.x;
            As[kq * 4 + 1][r] = v.y;
            As[kq * 4 + 2][r] = v.z;
            As[kq * 4 + 3][r] = v.w;
        }
        #pragma unroll
        for (int i = 0; i < 4; i++) {
            int id = tid + i * NTHREADS;
            int r = id >> 3;
            int kq = id & 7;
            int gc = col0 + r;
            float4 v = make_float4(0.f, 0.f, 0.f, 0.f);
            if (gc < NBLK) v = *(const float4*)(W + (size_t)gc * DIMK + k0 + kq * 4);
            Bs[kq * 4 + 0][r] = v.x;
            Bs[kq * 4 + 1][r] = v.y;
            Bs[kq * 4 + 2][r] = v.z;
            Bs[kq * 4 + 3][r] = v.w;
        }
        __syncthreads();
        #pragma unroll
        for (int k = 0; k < BK; k++) {
            float ra[TM], rb[TN];
            *(float4*)&ra[0] = *(const float4*)&As[k][tm * TM];
            *(float4*)&ra[4] = *(const float4*)&As[k][tm * TM + 4];
            *(float4*)&rb[0] = *(const float4*)&Bs[k][tn * TN];
            *(float4*)&rb[4] = *(const float4*)&Bs[k][tn * TN + 4];
            #pragma unroll
            for (int i = 0; i < TM; i++)
                #pragma unroll
                for (int j = 0; j < TN; j++) acc[i][j] += ra[i] * rb[j];
        }
        __syncthreads();
    }

    float local = 0.0f;
    #pragma unroll
    for (int i = 0; i < TM; i++) {
        int gi = row0 + tm * TM + i;
        #pragma unroll
        for (int j = 0; j < TN; j++) {
            int gj = col0 + tn * TN + j;
            if (gi < NBLK && gj < NBLK) {
                float d = acc[i][j] - (gi == gj ? 1.0f : 0.0f);
                local += d * d;
            }
        }
    }
    // block reduce
    __shared__ float sm[32];
    int lane = tid & 31, wid = tid >> 5;
    #pragma unroll
    for (int o = 16; o; o >>= 1) local += __shfl_down_sync(0xffffffffu, local, o);
    if (lane == 0) sm[wid] = local;
    __syncthreads();
    if (wid == 0) {
        float v = (lane < NTHREADS / 32) ? sm[lane] : 0.0f;
        #pragma unroll
        for (int o = 16; o; o >>= 1) v += __shfl_down_sync(0xffffffffu, v, o);
        if (lane == 0) atomicAdd(&g_div, v);
    }
}

// ---------------- finalize ----------------
template <typename Op>
__device__ __forceinline__ float block_reduce(float v, Op op, float ident, float* sbuf) {
    __syncthreads();
    int tid = threadIdx.x, lane = tid & 31, wid = tid >> 5;
    #pragma unroll
    for (int o = 16; o; o >>= 1) v = op(v, __shfl_down_sync(0xffffffffu, v, o));
    if (lane == 0) sbuf[wid] = v;
    __syncthreads();
    int nw = blockDim.x >> 5;
    if (wid == 0) {
        float w = (lane < nw) ? sbuf[lane] : ident;
        #pragma unroll
        for (int o = 16; o; o >>= 1) w = op(w, __shfl_down_sync(0xffffffffu, w, o));
        if (lane == 0) sbuf[0] = w;
    }
    __syncthreads();
    return sbuf[0];
}
struct OpSum { __device__ float operator()(float a, float b) const { return a + b; } };
struct OpMax { __device__ float operator()(float a, float b) const { return fmaxf(a, b); } };

__global__ void finalize_kernel(const int* __restrict__ mask, float* __restrict__ out) {
    __shared__ float sb_min[32];
    __shared__ float rbuf[32];
    __shared__ float smax[NB_HALF];
    __shared__ float sinvz[NB_HALF];

    int tid = threadIdx.x;
    int lane = tid & 31, wid = tid >> 5;

    // per-batch masked min of row maxima (32 warps <-> 32 batches)
    {
        int b = wid;
        float mn = CUDART_INF_F;
        for (int t = lane; t < T_PER_B; t += 32) {
            int gr = b * T_PER_B + t;
            if (mask[gr] > 0) mn = fminf(mn, dec_f(g_rowmax[gr]));
        }
        #pragma unroll
        for (int o = 16; o; o >>= 1) mn = fminf(mn, __shfl_down_sync(0xffffffffu, mn, o));
        if (lane == 0) sb_min[b] = mn;
    }
    __syncthreads();

    // softmax stats per half-batch
    for (int b = 0; b < NB_HALF; b++) {
        float mx = -CUDART_INF_F;
        for (int n = tid; n < NBLK; n += blockDim.x) mx = fmaxf(mx, g_s[b * NBLK + n]);
        mx = block_reduce(mx, OpMax(), -CUDART_INF_F, rbuf);
        if (tid == 0) smax[b] = mx;
        float se = 0.0f;
        for (int n = tid; n < NBLK; n += blockDim.x) se += expf(g_s[b * NBLK + n] - mx);
        se = block_reduce(se, OpSum(), 0.0f, rbuf);
        if (tid == 0) sinvz[b] = 1.0f / se;
        __syncthreads();
    }

    // u_loss = || mean_b softmax ||
    float usq = 0.0f;
    for (int n = tid; n < NBLK; n += blockDim.x) {
        float tmp = 0.0f;
        #pragma unroll
        for (int b = 0; b < NB_HALF; b++)
            tmp += expf(g_s[b * NBLK + n] - smax[b]) * sinvz[b];
        tmp *= (1.0f / (float)NB_HALF);
        usq += tmp * tmp;
    }
    usq = block_reduce(usq, OpSum(), 0.0f, rbuf);

    if (tid == 0) {
        float mean_min = 0.0f, mean_ab = 0.0f;
        for (int b = 0; b < NB_HALF; b++) { mean_min += sb_min[b]; mean_ab += sb_min[NB_HALF + b]; }
        mean_min *= (1.0f / (float)NB_HALF);
        mean_ab  *= (1.0f / (float)NB_HALF);
        out[0] = 0.2f * sqrtf(g_div);
        out[1] = 2.0f - mean_min + mean_ab;
        out[2] = 0.5f * sqrtf(usq);
    }
}

// ---------------- launch ----------------
extern "C" void kernel_launch(void* const* d_in, const int* in_sizes, int n_in,
                              void* d_out, int out_size) {
    const float* x = nullptr;
    const int*   mask = nullptr;
    const float* w = nullptr;
    for (int i = 0; i < n_in; i++) {
        if (in_sizes[i] == NROWS * DIMK)      x = (const float*)d_in[i];
        else if (in_sizes[i] == NROWS)        mask = (const int*)d_in[i];
        else if (in_sizes[i] == NBLK * DIMK)  w = (const float*)d_in[i];
    }
    float* out = (float*)d_out;

    float* invx_ptr; cudaGetSymbolAddress((void**)&invx_ptr, g_invx);
    float* invw_ptr; cudaGetSymbolAddress((void**)&invw_ptr, g_invw);

    init_kernel<<<(NROWS + 255) / 256, 256>>>();
    row_invnorm_kernel<<<NROWS, 256>>>(x, invx_ptr);
    row_invnorm_kernel<<<NBLK, 256>>>(w, invw_ptr);
    att_gemm_kernel<<<dim3(16, NROWS / BM), NTHREADS>>>(x, w, mask);
    div_gemm_kernel<<<dim3(16, 16), NTHREADS>>>(w);
    finalize_kernel<<<1, 1024>>>(mask, out);
}

// round 3
// speedup vs baseline: 1.9384x; 1.9384x over previous
#include <cuda_runtime.h>
#include <math_constants.h>
#include <cstdint>

#define DIMK   2048
#define NBLK   2000
#define NROWS  32768        // 32 * 1024
#define T_PER_B 1024
#define NB_HALF 16

#define BM 128
#define BN 128
#define BK 32
#define NITER (DIMK / BK)    // 64
#define NTH 256
#define ROWF 36              // padded smem row stride (floats)
#define TILE_F (128 * ROWF)  // 4608 floats per tile buffer

#define SMEM_FLOATS (4 * TILE_F + 1024)
#define SMEM_BYTES  (SMEM_FLOATS * 4)

// ---------------- device scratch ----------------
__device__ float        g_invx[NROWS];
__device__ float        g_invw[NBLK];
__device__ unsigned int g_rowmax[NROWS];
__device__ float        g_s[NB_HALF * NBLK];
__device__ float        g_div;

// ---------------- helpers ----------------
__device__ __forceinline__ unsigned int enc_f(float f) {
    unsigned int u = __float_as_uint(f);
    return (u & 0x80000000u) ? ~u : (u | 0x80000000u);
}
__device__ __forceinline__ float dec_f(unsigned int u) {
    unsigned int b = (u & 0x80000000u) ? (u ^ 0x80000000u) : ~u;
    return __uint_as_float(b);
}
__device__ __forceinline__ float tfq(float f) {   // fp32 -> tf32 bits (as float)
    uint32_t r;
    asm("cvt.rna.tf32.f32 %0, %1;" : "=r"(r) : "f"(f));
    return __uint_as_float(r);
}
__device__ __forceinline__ void mma_tf32(float* d, const uint32_t* a, const uint32_t* b) {
    asm volatile(
        "mma.sync.aligned.m16n8k8.row.col.f32.tf32.tf32.f32 "
        "{%0,%1,%2,%3}, {%4,%5,%6,%7}, {%8,%9}, {%0,%1,%2,%3};"
        : "+f"(d[0]), "+f"(d[1]), "+f"(d[2]), "+f"(d[3])
        : "r"(a[0]), "r"(a[1]), "r"(a[2]), "r"(a[3]), "r"(b[0]), "r"(b[1]));
}

// ---------------- init ----------------
__global__ void init_kernel() {
    int i = blockIdx.x * blockDim.x + threadIdx.x;
    if (i < NB_HALF * NBLK) g_s[i] = 0.0f;
    if (i < NROWS)          g_rowmax[i] = 0u;
    if (i == 0)             g_div = 0.0f;
}

// ---------------- per-row inverse L2 norm ----------------
__global__ void row_invnorm_kernel(const float* __restrict__ X, float* __restrict__ out) {
    int r = blockIdx.x;
    const float4* xp = (const float4*)(X + (size_t)r * DIMK);
    float ss = 0.0f;
    for (int i = threadIdx.x; i < DIMK / 4; i += blockDim.x) {
        float4 v = xp[i];
        ss += v.x * v.x + v.y * v.y + v.z * v.z + v.w * v.w;
    }
    __shared__ float sm[32];
    int lane = threadIdx.x & 31, wid = threadIdx.x >> 5;
    #pragma unroll
    for (int o = 16; o; o >>= 1) ss += __shfl_down_sync(0xffffffffu, ss, o);
    if (lane == 0) sm[wid] = ss;
    __syncthreads();
    if (wid == 0) {
        float v = (lane < (int)(blockDim.x >> 5)) ? sm[lane] : 0.0f;
        #pragma unroll
        for (int o = 16; o; o >>= 1) v += __shfl_down_sync(0xffffffffu, v, o);
        if (lane == 0) out[r] = 1.0f / fmaxf(sqrtf(v), 1e-12f);
    }
}

// ---------------- tf32 mma.sync GEMM, fused epilogues ----------------
// Smem k-permutation: element (r, k) of a 128x32 tile is stored at
//   tile[r * ROWF + (k & 3) * 8 + (k >> 2)]
// so each thread's 8 fragment k-values (k = c + 4j) are contiguous (2x float4).
template <bool IS_ATT>
__global__ __launch_bounds__(NTH)
void mma_gemm_kernel(const float* __restrict__ A, const float* __restrict__ B,
                     const int* __restrict__ mask) {
    extern __shared__ float smf[];
    float* Abuf[2] = { smf, smf + TILE_F };
    float* Bbuf[2] = { smf + 2 * TILE_F, smf + 3 * TILE_F };
    float* rowfac_s = smf + 4 * TILE_F;   // [128]
    float* invw_s   = rowfac_s + 128;     // [128]
    float* bias_s   = invw_s + 128;       // [128]
    float* csum_s   = bias_s + 128;       // [128]
    float* redm     = csum_s + 128;       // [128][4]

    const int tid  = threadIdx.x;
    const int lane = tid & 31, wid = tid >> 5;
    const int wm = wid >> 2, wn = wid & 3;
    const int g = lane >> 2, c = lane & 3;
    const int row0 = blockIdx.y * BM;
    const int col0 = blockIdx.x * BN;
    const bool fh = IS_ATT && (row0 < NROWS / 2);

    if (IS_ATT && tid < 128) {
        int gr = row0 + tid;
        rowfac_s[tid] = g_invx[gr] * (float)mask[gr];
        int n = col0 + tid;
        bool v = n < NBLK;
        invw_s[tid] = v ? g_invw[n] : 0.0f;
        bias_s[tid] = v ? 0.0f : -CUDART_INF_F;
        csum_s[tid] = 0.0f;
    }

    float d[4][4][4];
    #pragma unroll
    for (int i = 0; i < 4; i++)
        #pragma unroll
        for (int j = 0; j < 4; j++)
            #pragma unroll
            for (int r = 0; r < 4; r++) d[i][j][r] = 0.0f;

    float4 va[4], vb[4];

    auto ldg = [&](int s) {
        int k0 = s * BK;
        #pragma unroll
        for (int i = 0; i < 4; i++) {
            int idx = tid + i * NTH;
            int r = idx >> 3, q = idx & 7;
            float4 z = make_float4(0.f, 0.f, 0.f, 0.f);
            va[i] = (!IS_ATT && (row0 + r) >= NBLK) ? z
                  : *(const float4*)(A + (size_t)(row0 + r) * DIMK + k0 + q * 4);
            vb[i] = ((col0 + r) >= NBLK) ? z
                  : *(const float4*)(B + (size_t)(col0 + r) * DIMK + k0 + q * 4);
        }
    };
    auto sts = [&](int buf) {
        float* pa = Abuf[buf];
        float* pb = Bbuf[buf];
        #pragma unroll
        for (int i = 0; i < 4; i++) {
            int idx = tid + i * NTH;
            int r = idx >> 3, q = idx & 7;
            float* da = pa + r * ROWF + q;
            da[0] = tfq(va[i].x); da[8] = tfq(va[i].y); da[16] = tfq(va[i].z); da[24] = tfq(va[i].w);
            float* db = pb + r * ROWF + q;
            db[0] = tfq(vb[i].x); db[8] = tfq(vb[i].y); db[16] = tfq(vb[i].z); db[24] = tfq(vb[i].w);
        }
    };
    auto compute = [&](int buf) {
        const float* Ab = Abuf[buf];
        const float* Bb = Bbuf[buf];
        uint32_t b8[4][8];
        #pragma unroll
        for (int jn = 0; jn < 4; jn++) {
            const float* p = Bb + (wn * 32 + jn * 8 + g) * ROWF + c * 8;
            float4 lo = *(const float4*)p;
            float4 hi = *(const float4*)(p + 4);
            b8[jn][0] = __float_as_uint(lo.x); b8[jn][1] = __float_as_uint(lo.y);
            b8[jn][2] = __float_as_uint(lo.z); b8[jn][3] = __float_as_uint(lo.w);
            b8[jn][4] = __float_as_uint(hi.x); b8[jn][5] = __float_as_uint(hi.y);
            b8[jn][6] = __float_as_uint(hi.z); b8[jn][7] = __float_as_uint(hi.w);
        }
        #pragma unroll
        for (int i = 0; i < 4; i++) {
            const float* p0 = Ab + (wm * 64 + i * 16 + g) * ROWF + c * 8;
            const float* p1 = p0 + 8 * ROWF;
            float4 l0 = *(const float4*)p0, h0 = *(const float4*)(p0 + 4);
            float4 l1 = *(const float4*)p1, h1 = *(const float4*)(p1 + 4);
            uint32_t a0_[8] = { __float_as_uint(l0.x), __float_as_uint(l0.y),
                                __float_as_uint(l0.z), __float_as_uint(l0.w),
                                __float_as_uint(h0.x), __float_as_uint(h0.y),
                                __float_as_uint(h0.z), __float_as_uint(h0.w) };
            uint32_t a1_[8] = { __float_as_uint(l1.x), __float_as_uint(l1.y),
                                __float_as_uint(l1.z), __float_as_uint(l1.w),
                                __float_as_uint(h1.x), __float_as_uint(h1.y),
                                __float_as_uint(h1.z), __float_as_uint(h1.w) };
            #pragma unroll
            for (int t = 0; t < 4; t++) {
                uint32_t af[4] = { a0_[2 * t], a1_[2 * t], a0_[2 * t + 1], a1_[2 * t + 1] };
                #pragma unroll
                for (int jn = 0; jn < 4; jn++)
                    mma_tf32(d[i][jn], af, &b8[jn][2 * t]);
            }
        }
    };

    ldg(0);
    sts(0);
    __syncthreads();
    for (int s = 0; s < NITER; s++) {
        if (s + 1 < NITER) ldg(s + 1);
        compute(s & 1);
        if (s + 1 < NITER) sts((s + 1) & 1);
        __syncthreads();
    }

    // ---------------- epilogue ----------------
    if (IS_ATT) {
        // row maxima of acc*invw (with -inf bias on padded cols)
        #pragma unroll
        for (int i = 0; i < 4; i++) {
            float m0 = -CUDART_INF_F, m1 = -CUDART_INF_F;
            #pragma unroll
            for (int jn = 0; jn < 4; jn++) {
                int nb = wn * 32 + jn * 8 + 2 * c;
                float iw0 = invw_s[nb], iw1 = invw_s[nb + 1];
                float bz0 = bias_s[nb], bz1 = bias_s[nb + 1];
                m0 = fmaxf(m0, fmaxf(fmaf(d[i][jn][0], iw0, bz0), fmaf(d[i][jn][1], iw1, bz1)));
                m1 = fmaxf(m1, fmaxf(fmaf(d[i][jn][2], iw0, bz0), fmaf(d[i][jn][3], iw1, bz1)));
            }
            m0 = fmaxf(m0, __shfl_xor_sync(0xffffffffu, m0, 1));
            m0 = fmaxf(m0, __shfl_xor_sync(0xffffffffu, m0, 2));
            m1 = fmaxf(m1, __shfl_xor_sync(0xffffffffu, m1, 1));
            m1 = fmaxf(m1, __shfl_xor_sync(0xffffffffu, m1, 2));
            if (c == 0) {
                redm[(wm * 64 + i * 16 + g) * 4 + wn]     = m0;
                redm[(wm * 64 + i * 16 + g + 8) * 4 + wn] = m1;
            }
        }
        // masked column sums (first half only)
        if (fh) {
            float cs[4][2];
            #pragma unroll
            for (int jn = 0; jn < 4; jn++) { cs[jn][0] = 0.0f; cs[jn][1] = 0.0f; }
            #pragma unroll
            for (int i = 0; i < 4; i++) {
                float rf0 = rowfac_s[wm * 64 + i * 16 + g];
                float rf1 = rowfac_s[wm * 64 + i * 16 + g + 8];
                #pragma unroll
                for (int jn = 0; jn < 4; jn++) {
                    cs[jn][0] += d[i][jn][0] * rf0 + d[i][jn][2] * rf1;
                    cs[jn][1] += d[i][jn][1] * rf0 + d[i][jn][3] * rf1;
                }
            }
            #pragma unroll
            for (int jn = 0; jn < 4; jn++) {
                #pragma unroll
                for (int u = 0; u < 2; u++) {
                    float s = cs[jn][u];
                    s += __shfl_xor_sync(0xffffffffu, s, 4);
                    s += __shfl_xor_sync(0xffffffffu, s, 8);
                    s += __shfl_xor_sync(0xffffffffu, s, 16);
                    if (lane < 4) atomicAdd(&csum_s[wn * 32 + jn * 8 + 2 * c + u], s);
                }
            }
        }
        __syncthreads();
        if (tid < 128) {
            float m = fmaxf(fmaxf(redm[tid * 4 + 0], redm[tid * 4 + 1]),
                            fmaxf(redm[tid * 4 + 2], redm[tid * 4 + 3]));
            int gr = row0 + tid;
            atomicMax(&g_rowmax[gr], enc_f(m * g_invx[gr]));
        }
        if (fh && tid < 128) {
            int n = col0 + tid;
            if (n < NBLK) {
                int b = row0 >> 10;
                atomicAdd(&g_s[b * NBLK + n], csum_s[tid] * invw_s[tid]);
            }
        }
    } else {
        float acc = 0.0f;
        #pragma unroll
        for (int i = 0; i < 4; i++) {
            int m0 = row0 + wm * 64 + i * 16 + g;
            #pragma unroll
            for (int jn = 0; jn < 4; jn++) {
                int n0 = col0 + wn * 32 + jn * 8 + 2 * c;
                float e;
                e = d[i][jn][0] - ((m0 == n0     && m0 < NBLK) ? 1.0f : 0.0f); acc += e * e;
                e = d[i][jn][1] - ((m0 == n0 + 1 && m0 < NBLK) ? 1.0f : 0.0f); acc += e * e;
                e = d[i][jn][2] - ((m0 + 8 == n0     && m0 + 8 < NBLK) ? 1.0f : 0.0f); acc += e * e;
                e = d[i][jn][3] - ((m0 + 8 == n0 + 1 && m0 + 8 < NBLK) ? 1.0f : 0.0f); acc += e * e;
            }
        }
        #pragma unroll
        for (int o = 16; o; o >>= 1) acc += __shfl_xor_sync(0xffffffffu, acc, o);
        if (lane == 0) csum_s[wid] = acc;
        __syncthreads();
        if (tid == 0) {
            float t = 0.0f;
            #pragma unroll
            for (int w = 0; w < 8; w++) t += csum_s[w];
            atomicAdd(&g_div, t);
        }
    }
}

// ---------------- finalize ----------------
template <typename Op>
__device__ __forceinline__ float block_reduce(float v, Op op, float ident, float* sbuf) {
    __syncthreads();
    int tid = threadIdx.x, lane = tid & 31, wid = tid >> 5;
    #pragma unroll
    for (int o = 16; o; o >>= 1) v = op(v, __shfl_down_sync(0xffffffffu, v, o));
    if (lane == 0) sbuf[wid] = v;
    __syncthreads();
    int nw = blockDim.x >> 5;
    if (wid == 0) {
        float w = (lane < nw) ? sbuf[lane] : ident;
        #pragma unroll
        for (int o = 16; o; o >>= 1) w = op(w, __shfl_down_sync(0xffffffffu, w, o));
        if (lane == 0) sbuf[0] = w;
    }
    __syncthreads();
    return sbuf[0];
}
struct OpSum { __device__ float operator()(float a, float b) const { return a + b; } };
struct OpMax { __device__ float operator()(float a, float b) const { return fmaxf(a, b); } };

__global__ void finalize_kernel(const int* __restrict__ mask, float* __restrict__ out) {
    __shared__ float sb_min[32];
    __shared__ float rbuf[32];
    __shared__ float smax[NB_HALF];
    __shared__ float sinvz[NB_HALF];

    int tid = threadIdx.x;
    int lane = tid & 31, wid = tid >> 5;

    {
        int b = wid;
        float mn = CUDART_INF_F;
        for (int t = lane; t < T_PER_B; t += 32) {
            int gr = b * T_PER_B + t;
            if (mask[gr] > 0) mn = fminf(mn, dec_f(g_rowmax[gr]));
        }
        #pragma unroll
        for (int o = 16; o; o >>= 1) mn = fminf(mn, __shfl_down_sync(0xffffffffu, mn, o));
        if (lane == 0) sb_min[b] = mn;
    }
    __syncthreads();

    for (int b = 0; b < NB_HALF; b++) {
        float mx = -CUDART_INF_F;
        for (int n = tid; n < NBLK; n += blockDim.x) mx = fmaxf(mx, g_s[b * NBLK + n]);
        mx = block_reduce(mx, OpMax(), -CUDART_INF_F, rbuf);
        if (tid == 0) smax[b] = mx;
        float se = 0.0f;
        for (int n = tid; n < NBLK; n += blockDim.x) se += expf(g_s[b * NBLK + n] - mx);
        se = block_reduce(se, OpSum(), 0.0f, rbuf);
        if (tid == 0) sinvz[b] = 1.0f / se;
        __syncthreads();
    }

    float usq = 0.0f;
    for (int n = tid; n < NBLK; n += blockDim.x) {
        float tmp = 0.0f;
        #pragma unroll
        for (int b = 0; b < NB_HALF; b++)
            tmp += expf(g_s[b * NBLK + n] - smax[b]) * sinvz[b];
        tmp *= (1.0f / (float)NB_HALF);
        usq += tmp * tmp;
    }
    usq = block_reduce(usq, OpSum(), 0.0f, rbuf);

    if (tid == 0) {
        float mean_min = 0.0f, mean_ab = 0.0f;
        for (int b = 0; b < NB_HALF; b++) { mean_min += sb_min[b]; mean_ab += sb_min[NB_HALF + b]; }
        mean_min *= (1.0f / (float)NB_HALF);
        mean_ab  *= (1.0f / (float)NB_HALF);
        out[0] = 0.2f * sqrtf(g_div);
        out[1] = 2.0f - mean_min + mean_ab;
        out[2] = 0.5f * sqrtf(usq);
    }
}

// ---------------- launch ----------------
extern "C" void kernel_launch(void* const* d_in, const int* in_sizes, int n_in,
                              void* d_out, int out_size) {
    const float* x = nullptr;
    const int*   mask = nullptr;
    const float* w = nullptr;
    for (int i = 0; i < n_in; i++) {
        if (in_sizes[i] == NROWS * DIMK)      x = (const float*)d_in[i];
        else if (in_sizes[i] == NROWS)        mask = (const int*)d_in[i];
        else if (in_sizes[i] == NBLK * DIMK)  w = (const float*)d_in[i];
    }
    float* out = (float*)d_out;

    float* invx_ptr; cudaGetSymbolAddress((void**)&invx_ptr, g_invx);
    float* invw_ptr; cudaGetSymbolAddress((void**)&invw_ptr, g_invw);

    cudaFuncSetAttribute(mma_gemm_kernel<true>,  cudaFuncAttributeMaxDynamicSharedMemorySize, SMEM_BYTES);
    cudaFuncSetAttribute(mma_gemm_kernel<false>, cudaFuncAttributeMaxDynamicSharedMemorySize, SMEM_BYTES);

    init_kernel<<<(NROWS + 255) / 256, 256>>>();
    row_invnorm_kernel<<<NROWS, 256>>>(x, invx_ptr);
    row_invnorm_kernel<<<NBLK, 256>>>(w, invw_ptr);
    mma_gemm_kernel<true><<<dim3(16, 256), NTH, SMEM_BYTES>>>(x, w, mask);
    mma_gemm_kernel<false><<<dim3(16, 16), NTH, SMEM_BYTES>>>(w, w, nullptr);
    finalize_kernel<<<1, 1024>>>(mask, out);
}

// round 4
// speedup vs baseline: 2.9953x; 1.5452x over previous
#include <cuda_runtime.h>
#include <math_constants.h>
#include <cstdint>

#define DIMK   2048
#define NBLK   2000
#define NROWS  32768        // 32 * 1024
#define T_PER_B 1024
#define NB_HALF 16

#define BM 128
#define BN 128
#define BK 32
#define NITER (DIMK / BK)    // 64
#define NSTG 4               // cp.async pipeline depth
#define NTH 256

#define TILE_FLOATS (BM * BK)           // 4096 floats = 16KB
#define B_REGION    (NSTG * TILE_FLOATS) // float offset of B tiles
#define EPIL_OFF    (2 * NSTG * TILE_FLOATS) // 32768
#define SMEM_FLOATS (EPIL_OFF + 1024)
#define SMEM_BYTES  (SMEM_FLOATS * 4)   // 135168

// ---------------- device scratch ----------------
__device__ float        g_invx[NROWS];
__device__ float        g_invw[NBLK];
__device__ unsigned int g_rowmax[NROWS];
__device__ float        g_s[NB_HALF * NBLK];
__device__ float        g_div;

// ---------------- helpers ----------------
__device__ __forceinline__ unsigned int enc_f(float f) {
    unsigned int u = __float_as_uint(f);
    return (u & 0x80000000u) ? ~u : (u | 0x80000000u);
}
__device__ __forceinline__ float dec_f(unsigned int u) {
    unsigned int b = (u & 0x80000000u) ? (u ^ 0x80000000u) : ~u;
    return __uint_as_float(b);
}
__device__ __forceinline__ uint32_t smem_u32(const void* p) {
    uint32_t a;
    asm("{ .reg .u64 t; cvta.to.shared.u64 t, %1; cvt.u32.u64 %0, t; }" : "=r"(a) : "l"(p));
    return a;
}
__device__ __forceinline__ void cp16(uint32_t dst, const float* src, uint32_t sz) {
    asm volatile("cp.async.cg.shared.global [%0], [%1], 16, %2;"
                 :: "r"(dst), "l"(src), "r"(sz) : "memory");
}
#define CP_COMMIT() asm volatile("cp.async.commit_group;" ::: "memory")
#define CP_WAIT2()  asm volatile("cp.async.wait_group 2;" ::: "memory")
#define CP_WAIT0()  asm volatile("cp.async.wait_group 0;" ::: "memory")

// raw-fp32-operand tf32 mma (HW truncates mantissa)
__device__ __forceinline__ void mma_tf32(float* d,
        float a0, float a1, float a2, float a3, float b0, float b1) {
    asm volatile(
        "mma.sync.aligned.m16n8k8.row.col.f32.tf32.tf32.f32 "
        "{%0,%1,%2,%3}, {%4,%5,%6,%7}, {%8,%9}, {%0,%1,%2,%3};"
        : "+f"(d[0]), "+f"(d[1]), "+f"(d[2]), "+f"(d[3])
        : "r"(__float_as_uint(a0)), "r"(__float_as_uint(a1)),
          "r"(__float_as_uint(a2)), "r"(__float_as_uint(a3)),
          "r"(__float_as_uint(b0)), "r"(__float_as_uint(b1)));
}

// ---------------- init ----------------
__global__ void init_kernel() {
    int i = blockIdx.x * blockDim.x + threadIdx.x;
    if (i < NB_HALF * NBLK) g_s[i] = 0.0f;
    if (i < NROWS)          g_rowmax[i] = 0u;
    if (i == 0)             g_div = 0.0f;
}

// ---------------- per-row inverse L2 norm ----------------
__global__ void row_invnorm_kernel(const float* __restrict__ X, float* __restrict__ out) {
    int r = blockIdx.x;
    const float4* xp = (const float4*)(X + (size_t)r * DIMK);
    float ss = 0.0f;
    for (int i = threadIdx.x; i < DIMK / 4; i += blockDim.x) {
        float4 v = xp[i];
        ss += v.x * v.x + v.y * v.y + v.z * v.z + v.w * v.w;
    }
    __shared__ float sm[32];
    int lane = threadIdx.x & 31, wid = threadIdx.x >> 5;
    #pragma unroll
    for (int o = 16; o; o >>= 1) ss += __shfl_down_sync(0xffffffffu, ss, o);
    if (lane == 0) sm[wid] = ss;
    __syncthreads();
    if (wid == 0) {
        float v = (lane < (int)(blockDim.x >> 5)) ? sm[lane] : 0.0f;
        #pragma unroll
        for (int o = 16; o; o >>= 1) v += __shfl_down_sync(0xffffffffu, v, o);
        if (lane == 0) out[r] = 1.0f / fmaxf(sqrtf(v), 1e-12f);
    }
}

// ---------------- tf32 mma.sync GEMM with cp.async 4-stage pipeline ----------------
// smem tile: row-major, 32 floats/row (128B = 8 granules of 16B).
// Granule swizzle: phys_q = q ^ fxor(r), fxor(r) = (r&3) ^ ((r&1)<<2).
// mma k-slot mapping: thread (g,c) supplies k' = {4c+2u', 4c+2u'+1} per mma —
// a per-warp bijection, identical for A and B, so the dot product is exact.
template <bool IS_ATT>
__global__ __launch_bounds__(NTH)
void mma_gemm_kernel(const float* __restrict__ A, const float* __restrict__ B,
                     const int* __restrict__ mask) {
    extern __shared__ float smf[];
    float* rowfac_s = smf + EPIL_OFF;     // [128]
    float* invw_s   = rowfac_s + 128;     // [128]
    float* bias_s   = invw_s + 128;       // [128]
    float* csum_s   = bias_s + 128;       // [128]
    float* redm     = csum_s + 128;       // [128][4]

    const int tid  = threadIdx.x;
    const int lane = tid & 31, wid = tid >> 5;
    const int wm = wid >> 2, wn = wid & 3;
    const int g = lane >> 2, c = lane & 3;
    const int row0 = blockIdx.y * BM;
    const int col0 = blockIdx.x * BN;
    const bool fh = IS_ATT && (row0 < NROWS / 2);

    if (IS_ATT && tid < 128) {
        int gr = row0 + tid;
        rowfac_s[tid] = g_invx[gr] * (float)mask[gr];
        int n = col0 + tid;
        bool v = n < NBLK;
        invw_s[tid] = v ? g_invw[n] : 0.0f;
        bias_s[tid] = v ? 0.0f : -CUDART_INF_F;
        csum_s[tid] = 0.0f;
    }

    // ---- cp.async setup ----
    const int r_ld = tid >> 1;
    const int h    = tid & 1;
    const int fx   = (r_ld & 3) ^ ((r_ld & 1) << 2);
    const uint32_t sbase = smem_u32(smf);
    uint32_t a_dst[4], b_dst[4];
    #pragma unroll
    for (int j = 0; j < 4; j++) {
        int q = h * 4 + j;
        uint32_t off = (uint32_t)r_ld * 128u + (uint32_t)((q ^ fx) * 16);
        a_dst[j] = sbase + off;
        b_dst[j] = sbase + (uint32_t)(B_REGION * 4) + off;
    }
    const bool a_ok = IS_ATT || (row0 + r_ld) < NBLK;
    const bool b_ok = (col0 + r_ld) < NBLK;
    const uint32_t a_sz = a_ok ? 16u : 0u;
    const uint32_t b_sz = b_ok ? 16u : 0u;
    const float* a_src = A + (size_t)(a_ok ? (row0 + r_ld) : 0) * DIMK + h * 16;
    const float* b_src = B + (size_t)(b_ok ? (col0 + r_ld) : 0) * DIMK + h * 16;

    auto load_stage = [&](int s) {
        uint32_t ab = (uint32_t)((s & (NSTG - 1)) * TILE_FLOATS * 4);
        const float* as = a_src + s * BK;
        const float* bs = b_src + s * BK;
        #pragma unroll
        for (int j = 0; j < 4; j++) {
            cp16(a_dst[j] + ab, as + j * 4, a_sz);
            cp16(b_dst[j] + ab, bs + j * 4, b_sz);
        }
    };

    // ---- accumulators ----
    float d[4][4][4];
    #pragma unroll
    for (int i = 0; i < 4; i++)
        #pragma unroll
        for (int j = 0; j < 4; j++)
            #pragma unroll
            for (int r = 0; r < 4; r++) d[i][j][r] = 0.0f;

    const int p4  = (c ^ ((g & 3) ^ ((g & 1) << 2))) * 4;  // float offset of granule
    const int p4x = p4 ^ 16;

    auto compute = [&](int buf) {
        const float* Ab = smf + buf * TILE_FLOATS;
        const float* Bb = smf + B_REGION + buf * TILE_FLOATS;
        float4 bl[4], bh[4];
        #pragma unroll
        for (int jn = 0; jn < 4; jn++) {
            const float* base = Bb + (wn * 32 + jn * 8 + g) * 32;
            bl[jn] = *(const float4*)(base + p4);
            bh[jn] = *(const float4*)(base + p4x);
        }
        #pragma unroll
        for (int i = 0; i < 4; i++) {
            const float* base = Ab + (wm * 64 + i * 16 + g) * 32;
            float4 al0 = *(const float4*)(base + p4);
            float4 ah0 = *(const float4*)(base + p4x);
            float4 al1 = *(const float4*)(base + 256 + p4);
            float4 ah1 = *(const float4*)(base + 256 + p4x);
            #pragma unroll
            for (int jn = 0; jn < 4; jn++) {
                mma_tf32(d[i][jn], al0.x, al1.x, al0.y, al1.y, bl[jn].x, bl[jn].y);
                mma_tf32(d[i][jn], al0.z, al1.z, al0.w, al1.w, bl[jn].z, bl[jn].w);
                mma_tf32(d[i][jn], ah0.x, ah1.x, ah0.y, ah1.y, bh[jn].x, bh[jn].y);
                mma_tf32(d[i][jn], ah0.z, ah1.z, ah0.w, ah1.w, bh[jn].z, bh[jn].w);
            }
        }
    };

    // ---- pipeline ----
    load_stage(0); CP_COMMIT();
    load_stage(1); CP_COMMIT();
    load_stage(2); CP_COMMIT();
    for (int s = 0; s < NITER; s++) {
        CP_WAIT2();
        __syncthreads();
        if (s + NSTG - 1 < NITER) load_stage(s + NSTG - 1);
        CP_COMMIT();
        compute(s & (NSTG - 1));
    }
    CP_WAIT0();

    // ---------------- epilogue ----------------
    if (IS_ATT) {
        #pragma unroll
        for (int i = 0; i < 4; i++) {
            float m0 = -CUDART_INF_F, m1 = -CUDART_INF_F;
            #pragma unroll
            for (int jn = 0; jn < 4; jn++) {
                int nb = wn * 32 + jn * 8 + 2 * c;
                float iw0 = invw_s[nb], iw1 = invw_s[nb + 1];
                float bz0 = bias_s[nb], bz1 = bias_s[nb + 1];
                m0 = fmaxf(m0, fmaxf(fmaf(d[i][jn][0], iw0, bz0), fmaf(d[i][jn][1], iw1, bz1)));
                m1 = fmaxf(m1, fmaxf(fmaf(d[i][jn][2], iw0, bz0), fmaf(d[i][jn][3], iw1, bz1)));
            }
            m0 = fmaxf(m0, __shfl_xor_sync(0xffffffffu, m0, 1));
            m0 = fmaxf(m0, __shfl_xor_sync(0xffffffffu, m0, 2));
            m1 = fmaxf(m1, __shfl_xor_sync(0xffffffffu, m1, 1));
            m1 = fmaxf(m1, __shfl_xor_sync(0xffffffffu, m1, 2));
            if (c == 0) {
                redm[(wm * 64 + i * 16 + g) * 4 + wn]     = m0;
                redm[(wm * 64 + i * 16 + g + 8) * 4 + wn] = m1;
            }
        }
        if (fh) {
            float cs[4][2];
            #pragma unroll
            for (int jn = 0; jn < 4; jn++) { cs[jn][0] = 0.0f; cs[jn][1] = 0.0f; }
            #pragma unroll
            for (int i = 0; i < 4; i++) {
                float rf0 = rowfac_s[wm * 64 + i * 16 + g];
                float rf1 = rowfac_s[wm * 64 + i * 16 + g + 8];
                #pragma unroll
                for (int jn = 0; jn < 4; jn++) {
                    cs[jn][0] += d[i][jn][0] * rf0 + d[i][jn][2] * rf1;
                    cs[jn][1] += d[i][jn][1] * rf0 + d[i][jn][3] * rf1;
                }
            }
            #pragma unroll
            for (int jn = 0; jn < 4; jn++) {
                #pragma unroll
                for (int u = 0; u < 2; u++) {
                    float s = cs[jn][u];
                    s += __shfl_xor_sync(0xffffffffu, s, 4);
                    s += __shfl_xor_sync(0xffffffffu, s, 8);
                    s += __shfl_xor_sync(0xffffffffu, s, 16);
                    if (lane < 4) atomicAdd(&csum_s[wn * 32 + jn * 8 + 2 * c + u], s);
                }
            }
        }
        __syncthreads();
        if (tid < 128) {
            float m = fmaxf(fmaxf(redm[tid * 4 + 0], redm[tid * 4 + 1]),
                            fmaxf(redm[tid * 4 + 2], redm[tid * 4 + 3]));
            int gr = row0 + tid;
            atomicMax(&g_rowmax[gr], enc_f(m * g_invx[gr]));
        }
        if (fh && tid < 128) {
            int n = col0 + tid;
            if (n < NBLK) {
                int b = row0 >> 10;
                atomicAdd(&g_s[b * NBLK + n], csum_s[tid] * invw_s[tid]);
            }
        }
    } else {
        float acc = 0.0f;
        #pragma unroll
        for (int i = 0; i < 4; i++) {
            int m0 = row0 + wm * 64 + i * 16 + g;
            #pragma unroll
            for (int jn = 0; jn < 4; jn++) {
                int n0 = col0 + wn * 32 + jn * 8 + 2 * c;
                float e;
                e = d[i][jn][0] - ((m0 == n0     && m0 < NBLK) ? 1.0f : 0.0f); acc += e * e;
                e = d[i][jn][1] - ((m0 == n0 + 1 && m0 < NBLK) ? 1.0f : 0.0f); acc += e * e;
                e = d[i][jn][2] - ((m0 + 8 == n0     && m0 + 8 < NBLK) ? 1.0f : 0.0f); acc += e * e;
                e = d[i][jn][3] - ((m0 + 8 == n0 + 1 && m0 + 8 < NBLK) ? 1.0f : 0.0f); acc += e * e;
            }
        }
        #pragma unroll
        for (int o = 16; o; o >>= 1) acc += __shfl_xor_sync(0xffffffffu, acc, o);
        if (lane == 0) csum_s[wid] = acc;
        __syncthreads();
        if (tid == 0) {
            float t = 0.0f;
            #pragma unroll
            for (int w = 0; w < 8; w++) t += csum_s[w];
            atomicAdd(&g_div, t);
        }
    }
}

// ---------------- finalize ----------------
template <typename Op>
__device__ __forceinline__ float block_reduce(float v, Op op, float ident, float* sbuf) {
    __syncthreads();
    int tid = threadIdx.x, lane = tid & 31, wid = tid >> 5;
    #pragma unroll
    for (int o = 16; o; o >>= 1) v = op(v, __shfl_down_sync(0xffffffffu, v, o));
    if (lane == 0) sbuf[wid] = v;
    __syncthreads();
    int nw = blockDim.x >> 5;
    if (wid == 0) {
        float w = (lane < nw) ? sbuf[lane] : ident;
        #pragma unroll
        for (int o = 16; o; o >>= 1) w = op(w, __shfl_down_sync(0xffffffffu, w, o));
        if (lane == 0) sbuf[0] = w;
    }
    __syncthreads();
    return sbuf[0];
}
struct OpSum { __device__ float operator()(float a, float b) const { return a + b; } };
struct OpMax { __device__ float operator()(float a, float b) const { return fmaxf(a, b); } };

__global__ void finalize_kernel(const int* __restrict__ mask, float* __restrict__ out) {
    __shared__ float sb_min[32];
    __shared__ float rbuf[32];
    __shared__ float smax[NB_HALF];
    __shared__ float sinvz[NB_HALF];

    int tid = threadIdx.x;
    int lane = tid & 31, wid = tid >> 5;

    {
        int b = wid;
        float mn = CUDART_INF_F;
        for (int t = lane; t < T_PER_B; t += 32) {
            int gr = b * T_PER_B + t;
            if (mask[gr] > 0) mn = fminf(mn, dec_f(g_rowmax[gr]));
        }
        #pragma unroll
        for (int o = 16; o; o >>= 1) mn = fminf(mn, __shfl_down_sync(0xffffffffu, mn, o));
        if (lane == 0) sb_min[b] = mn;
    }
    __syncthreads();

    for (int b = 0; b < NB_HALF; b++) {
        float mx = -CUDART_INF_F;
        for (int n = tid; n < NBLK; n += blockDim.x) mx = fmaxf(mx, g_s[b * NBLK + n]);
        mx = block_reduce(mx, OpMax(), -CUDART_INF_F, rbuf);
        if (tid == 0) smax[b] = mx;
        float se = 0.0f;
        for (int n = tid; n < NBLK; n += blockDim.x) se += expf(g_s[b * NBLK + n] - mx);
        se = block_reduce(se, OpSum(), 0.0f, rbuf);
        if (tid == 0) sinvz[b] = 1.0f / se;
        __syncthreads();
    }

    float usq = 0.0f;
    for (int n = tid; n < NBLK; n += blockDim.x) {
        float tmp = 0.0f;
        #pragma unroll
        for (int b = 0; b < NB_HALF; b++)
            tmp += expf(g_s[b * NBLK + n] - smax[b]) * sinvz[b];
        tmp *= (1.0f / (float)NB_HALF);
        usq += tmp * tmp;
    }
    usq = block_reduce(usq, OpSum(), 0.0f, rbuf);

    if (tid == 0) {
        float mean_min = 0.0f, mean_ab = 0.0f;
        for (int b = 0; b < NB_HALF; b++) { mean_min += sb_min[b]; mean_ab += sb_min[NB_HALF + b]; }
        mean_min *= (1.0f / (float)NB_HALF);
        mean_ab  *= (1.0f / (float)NB_HALF);
        out[0] = 0.2f * sqrtf(g_div);
        out[1] = 2.0f - mean_min + mean_ab;
        out[2] = 0.5f * sqrtf(usq);
    }
}

// ---------------- launch ----------------
extern "C" void kernel_launch(void* const* d_in, const int* in_sizes, int n_in,
                              void* d_out, int out_size) {
    const float* x = nullptr;
    const int*   mask = nullptr;
    const float* w = nullptr;
    for (int i = 0; i < n_in; i++) {
        if (in_sizes[i] == NROWS * DIMK)      x = (const float*)d_in[i];
        else if (in_sizes[i] == NROWS)        mask = (const int*)d_in[i];
        else if (in_sizes[i] == NBLK * DIMK)  w = (const float*)d_in[i];
    }
    float* out = (float*)d_out;

    float* invx_ptr; cudaGetSymbolAddress((void**)&invx_ptr, g_invx);
    float* invw_ptr; cudaGetSymbolAddress((void**)&invw_ptr, g_invw);

    cudaFuncSetAttribute(mma_gemm_kernel<true>,  cudaFuncAttributeMaxDynamicSharedMemorySize, SMEM_BYTES);
    cudaFuncSetAttribute(mma_gemm_kernel<false>, cudaFuncAttributeMaxDynamicSharedMemorySize, SMEM_BYTES);

    init_kernel<<<(NROWS + 255) / 256, 256>>>();
    row_invnorm_kernel<<<NROWS, 256>>>(x, invx_ptr);
    row_invnorm_kernel<<<NBLK, 256>>>(w, invw_ptr);
    mma_gemm_kernel<true><<<dim3(16, 256), NTH, SMEM_BYTES>>>(x, w, mask);
    mma_gemm_kernel<false><<<dim3(16, 16), NTH, SMEM_BYTES>>>(w, w, nullptr);
    finalize_kernel<<<1, 1024>>>(mask, out);
}

// round 5
// speedup vs baseline: 3.3596x; 1.1216x over previous
#include <cuda_runtime.h>
#include <math_constants.h>
#include <cstdint>

#define DIMK   2048
#define NBLK   2000
#define NROWS  32768        // 32 * 1024
#define T_PER_B 1024
#define NB_HALF 16

#define BM 128
#define BN 128
#define BK 32
#define NITER (DIMK / BK)    // 64
#define NSTG 3               // cp.async pipeline depth
#define NTH 256

#define TILE_FLOATS (BM * BK)            // 4096 floats = 16KB
#define B_REGION    (NSTG * TILE_FLOATS) // float offset of B tiles
#define EPIL_OFF    (2 * NSTG * TILE_FLOATS) // 24576
#define SMEM_FLOATS (EPIL_OFF + 1024)
#define SMEM_BYTES  (SMEM_FLOATS * 4)    // 102400 -> 2 CTAs/SM

// ---------------- device scratch ----------------
__device__ float        g_invx[NROWS];
__device__ float        g_invw[NBLK];
__device__ unsigned int g_rowmax[NROWS];
__device__ float        g_s[NB_HALF * NBLK];
__device__ float        g_div;

// ---------------- helpers ----------------
__device__ __forceinline__ unsigned int enc_f(float f) {
    unsigned int u = __float_as_uint(f);
    return (u & 0x80000000u) ? ~u : (u | 0x80000000u);
}
__device__ __forceinline__ float dec_f(unsigned int u) {
    unsigned int b = (u & 0x80000000u) ? (u ^ 0x80000000u) : ~u;
    return __uint_as_float(b);
}
__device__ __forceinline__ uint32_t smem_u32(const void* p) {
    uint32_t a;
    asm("{ .reg .u64 t; cvta.to.shared.u64 t, %1; cvt.u32.u64 %0, t; }" : "=r"(a) : "l"(p));
    return a;
}
__device__ __forceinline__ void cp16(uint32_t dst, const float* src, uint32_t sz) {
    asm volatile("cp.async.cg.shared.global [%0], [%1], 16, %2;"
                 :: "r"(dst), "l"(src), "r"(sz) : "memory");
}
#define CP_COMMIT() asm volatile("cp.async.commit_group;" ::: "memory")
#define CP_WAIT1()  asm volatile("cp.async.wait_group 1;" ::: "memory")
#define CP_WAIT0()  asm volatile("cp.async.wait_group 0;" ::: "memory")

// raw-fp32-operand tf32 mma (HW truncates mantissa)
__device__ __forceinline__ void mma_tf32(float* d,
        float a0, float a1, float a2, float a3, float b0, float b1) {
    asm volatile(
        "mma.sync.aligned.m16n8k8.row.col.f32.tf32.tf32.f32 "
        "{%0,%1,%2,%3}, {%4,%5,%6,%7}, {%8,%9}, {%0,%1,%2,%3};"
        : "+f"(d[0]), "+f"(d[1]), "+f"(d[2]), "+f"(d[3])
        : "r"(__float_as_uint(a0)), "r"(__float_as_uint(a1)),
          "r"(__float_as_uint(a2)), "r"(__float_as_uint(a3)),
          "r"(__float_as_uint(b0)), "r"(__float_as_uint(b1)));
}

// ---------------- init ----------------
__global__ void init_kernel() {
    int i = blockIdx.x * blockDim.x + threadIdx.x;
    if (i < NB_HALF * NBLK) g_s[i] = 0.0f;
    if (i < NROWS)          g_rowmax[i] = 0u;
    if (i == 0)             g_div = 0.0f;
}

// ---------------- per-row inverse L2 norm ----------------
__global__ void row_invnorm_kernel(const float* __restrict__ X, float* __restrict__ out) {
    int r = blockIdx.x;
    const float4* xp = (const float4*)(X + (size_t)r * DIMK);
    float ss = 0.0f;
    for (int i = threadIdx.x; i < DIMK / 4; i += blockDim.x) {
        float4 v = xp[i];
        ss += v.x * v.x + v.y * v.y + v.z * v.z + v.w * v.w;
    }
    __shared__ float sm[32];
    int lane = threadIdx.x & 31, wid = threadIdx.x >> 5;
    #pragma unroll
    for (int o = 16; o; o >>= 1) ss += __shfl_down_sync(0xffffffffu, ss, o);
    if (lane == 0) sm[wid] = ss;
    __syncthreads();
    if (wid == 0) {
        float v = (lane < (int)(blockDim.x >> 5)) ? sm[lane] : 0.0f;
        #pragma unroll
        for (int o = 16; o; o >>= 1) v += __shfl_down_sync(0xffffffffu, v, o);
        if (lane == 0) out[r] = 1.0f / fmaxf(sqrtf(v), 1e-12f);
    }
}

// ---------------- tf32 mma.sync GEMM with cp.async 3-stage pipeline, 2 CTAs/SM ----------------
// smem tile: row-major, 32 floats/row (128B = 8 granules of 16B).
// Granule swizzle: phys_q = q ^ fxor(r), fxor(r) = (r&3) ^ ((r&1)<<2).
template <bool IS_ATT>
__global__ __launch_bounds__(NTH, 2)
void mma_gemm_kernel(const float* __restrict__ A, const float* __restrict__ B,
                     const int* __restrict__ mask) {
    extern __shared__ float smf[];
    float* rowfac_s = smf + EPIL_OFF;     // [128]
    float* invw_s   = rowfac_s + 128;     // [128]
    float* bias_s   = invw_s + 128;       // [128]
    float* csum_s   = bias_s + 128;       // [128]
    float* redm     = csum_s + 128;       // [128][4]

    const int tid  = threadIdx.x;
    const int lane = tid & 31, wid = tid >> 5;
    const int wm = wid >> 2, wn = wid & 3;
    const int g = lane >> 2, c = lane & 3;
    const int row0 = blockIdx.y * BM;
    const int col0 = blockIdx.x * BN;
    const bool fh = IS_ATT && (row0 < NROWS / 2);

    if (IS_ATT && tid < 128) {
        int gr = row0 + tid;
        rowfac_s[tid] = g_invx[gr] * (float)mask[gr];
        int n = col0 + tid;
        bool v = n < NBLK;
        invw_s[tid] = v ? g_invw[n] : 0.0f;
        bias_s[tid] = v ? 0.0f : -CUDART_INF_F;
        csum_s[tid] = 0.0f;
    }

    // ---- cp.async setup ----
    const int r_ld = tid >> 1;
    const int h    = tid & 1;
    const int fx   = (r_ld & 3) ^ ((r_ld & 1) << 2);
    const uint32_t sbase = smem_u32(smf);
    uint32_t a_dst[4], b_dst[4];
    #pragma unroll
    for (int j = 0; j < 4; j++) {
        int q = h * 4 + j;
        uint32_t off = (uint32_t)r_ld * 128u + (uint32_t)((q ^ fx) * 16);
        a_dst[j] = sbase + off;
        b_dst[j] = sbase + (uint32_t)(B_REGION * 4) + off;
    }
    const bool a_ok = IS_ATT || (row0 + r_ld) < NBLK;
    const bool b_ok = (col0 + r_ld) < NBLK;
    const uint32_t a_sz = a_ok ? 16u : 0u;
    const uint32_t b_sz = b_ok ? 16u : 0u;
    const float* a_src = A + (size_t)(a_ok ? (row0 + r_ld) : 0) * DIMK + h * 16;
    const float* b_src = B + (size_t)(b_ok ? (col0 + r_ld) : 0) * DIMK + h * 16;

    auto load_stage = [&](int s) {
        uint32_t ab = (uint32_t)((s % NSTG) * (TILE_FLOATS * 4));
        const float* as = a_src + s * BK;
        const float* bs = b_src + s * BK;
        #pragma unroll
        for (int j = 0; j < 4; j++) {
            cp16(a_dst[j] + ab, as + j * 4, a_sz);
            cp16(b_dst[j] + ab, bs + j * 4, b_sz);
        }
    };

    // ---- accumulators ----
    float d[4][4][4];
    #pragma unroll
    for (int i = 0; i < 4; i++)
        #pragma unroll
        for (int j = 0; j < 4; j++)
            #pragma unroll
            for (int r = 0; r < 4; r++) d[i][j][r] = 0.0f;

    const int p4  = (c ^ ((g & 3) ^ ((g & 1) << 2))) * 4;  // float offset of granule
    const int p4x = p4 ^ 16;

    auto compute = [&](int buf) {
        const float* Ab = smf + buf * TILE_FLOATS;
        const float* Bb = smf + B_REGION + buf * TILE_FLOATS;
        float4 bl[4], bh[4];
        #pragma unroll
        for (int jn = 0; jn < 4; jn++) {
            const float* base = Bb + (wn * 32 + jn * 8 + g) * 32;
            bl[jn] = *(const float4*)(base + p4);
            bh[jn] = *(const float4*)(base + p4x);
        }
        #pragma unroll
        for (int i = 0; i < 4; i++) {
            const float* base = Ab + (wm * 64 + i * 16 + g) * 32;
            float4 al0 = *(const float4*)(base + p4);
            float4 ah0 = *(const float4*)(base + p4x);
            float4 al1 = *(const float4*)(base + 256 + p4);
            float4 ah1 = *(const float4*)(base + 256 + p4x);
            #pragma unroll
            for (int jn = 0; jn < 4; jn++) {
                mma_tf32(d[i][jn], al0.x, al1.x, al0.y, al1.y, bl[jn].x, bl[jn].y);
                mma_tf32(d[i][jn], al0.z, al1.z, al0.w, al1.w, bl[jn].z, bl[jn].w);
                mma_tf32(d[i][jn], ah0.x, ah1.x, ah0.y, ah1.y, bh[jn].x, bh[jn].y);
                mma_tf32(d[i][jn], ah0.z, ah1.z, ah0.w, ah1.w, bh[jn].z, bh[jn].w);
            }
        }
    };

    // ---- pipeline (3 buffers, 2 groups in flight) ----
    load_stage(0); CP_COMMIT();
    load_stage(1); CP_COMMIT();
    int buf = 0;
    for (int s = 0; s < NITER; s++) {
        CP_WAIT1();
        __syncthreads();
        if (s + 2 < NITER) load_stage(s + 2);
        CP_COMMIT();
        compute(buf);
        buf = (buf == NSTG - 1) ? 0 : buf + 1;
    }
    CP_WAIT0();

    // ---------------- epilogue ----------------
    if (IS_ATT) {
        #pragma unroll
        for (int i = 0; i < 4; i++) {
            float m0 = -CUDART_INF_F, m1 = -CUDART_INF_F;
            #pragma unroll
            for (int jn = 0; jn < 4; jn++) {
                int nb = wn * 32 + jn * 8 + 2 * c;
                float iw0 = invw_s[nb], iw1 = invw_s[nb + 1];
                float bz0 = bias_s[nb], bz1 = bias_s[nb + 1];
                m0 = fmaxf(m0, fmaxf(fmaf(d[i][jn][0], iw0, bz0), fmaf(d[i][jn][1], iw1, bz1)));
                m1 = fmaxf(m1, fmaxf(fmaf(d[i][jn][2], iw0, bz0), fmaf(d[i][jn][3], iw1, bz1)));
            }
            m0 = fmaxf(m0, __shfl_xor_sync(0xffffffffu, m0, 1));
            m0 = fmaxf(m0, __shfl_xor_sync(0xffffffffu, m0, 2));
            m1 = fmaxf(m1, __shfl_xor_sync(0xffffffffu, m1, 1));
            m1 = fmaxf(m1, __shfl_xor_sync(0xffffffffu, m1, 2));
            if (c == 0) {
                redm[(wm * 64 + i * 16 + g) * 4 + wn]     = m0;
                redm[(wm * 64 + i * 16 + g + 8) * 4 + wn] = m1;
            }
        }
        if (fh) {
            float cs[4][2];
            #pragma unroll
            for (int jn = 0; jn < 4; jn++) { cs[jn][0] = 0.0f; cs[jn][1] = 0.0f; }
            #pragma unroll
            for (int i = 0; i < 4; i++) {
                float rf0 = rowfac_s[wm * 64 + i * 16 + g];
                float rf1 = rowfac_s[wm * 64 + i * 16 + g + 8];
                #pragma unroll
                for (int jn = 0; jn < 4; jn++) {
                    cs[jn][0] += d[i][jn][0] * rf0 + d[i][jn][2] * rf1;
                    cs[jn][1] += d[i][jn][1] * rf0 + d[i][jn][3] * rf1;
                }
            }
            #pragma unroll
            for (int jn = 0; jn < 4; jn++) {
                #pragma unroll
                for (int u = 0; u < 2; u++) {
                    float s = cs[jn][u];
                    s += __shfl_xor_sync(0xffffffffu, s, 4);
                    s += __shfl_xor_sync(0xffffffffu, s, 8);
                    s += __shfl_xor_sync(0xffffffffu, s, 16);
                    if (lane < 4) atomicAdd(&csum_s[wn * 32 + jn * 8 + 2 * c + u], s);
                }
            }
        }
        __syncthreads();
        if (tid < 128) {
            float m = fmaxf(fmaxf(redm[tid * 4 + 0], redm[tid * 4 + 1]),
                            fmaxf(redm[tid * 4 + 2], redm[tid * 4 + 3]));
            int gr = row0 + tid;
            atomicMax(&g_rowmax[gr], enc_f(m * g_invx[gr]));
        }
        if (fh && tid < 128) {
            int n = col0 + tid;
            if (n < NBLK) {
                int b = row0 >> 10;
                atomicAdd(&g_s[b * NBLK + n], csum_s[tid] * invw_s[tid]);
            }
        }
    } else {
        float acc = 0.0f;
        #pragma unroll
        for (int i = 0; i < 4; i++) {
            int m0 = row0 + wm * 64 + i * 16 + g;
            #pragma unroll
            for (int jn = 0; jn < 4; jn++) {
                int n0 = col0 + wn * 32 + jn * 8 + 2 * c;
                float e;
                e = d[i][jn][0] - ((m0 == n0     && m0 < NBLK) ? 1.0f : 0.0f); acc += e * e;
                e = d[i][jn][1] - ((m0 == n0 + 1 && m0 < NBLK) ? 1.0f : 0.0f); acc += e * e;
                e = d[i][jn][2] - ((m0 + 8 == n0     && m0 + 8 < NBLK) ? 1.0f : 0.0f); acc += e * e;
                e = d[i][jn][3] - ((m0 + 8 == n0 + 1 && m0 + 8 < NBLK) ? 1.0f : 0.0f); acc += e * e;
            }
        }
        #pragma unroll
        for (int o = 16; o; o >>= 1) acc += __shfl_xor_sync(0xffffffffu, acc, o);
        if (lane == 0) csum_s[wid] = acc;
        __syncthreads();
        if (tid == 0) {
            float t = 0.0f;
            #pragma unroll
            for (int w = 0; w < 8; w++) t += csum_s[w];
            atomicAdd(&g_div, t);
        }
    }
}

// ---------------- finalize ----------------
template <typename Op>
__device__ __forceinline__ float block_reduce(float v, Op op, float ident, float* sbuf) {
    __syncthreads();
    int tid = threadIdx.x, lane = tid & 31, wid = tid >> 5;
    #pragma unroll
    for (int o = 16; o; o >>= 1) v = op(v, __shfl_down_sync(0xffffffffu, v, o));
    if (lane == 0) sbuf[wid] = v;
    __syncthreads();
    int nw = blockDim.x >> 5;
    if (wid == 0) {
        float w = (lane < nw) ? sbuf[lane] : ident;
        #pragma unroll
        for (int o = 16; o; o >>= 1) w = op(w, __shfl_down_sync(0xffffffffu, w, o));
        if (lane == 0) sbuf[0] = w;
    }
    __syncthreads();
    return sbuf[0];
}
struct OpSum { __device__ float operator()(float a, float b) const { return a + b; } };
struct OpMax { __device__ float operator()(float a, float b) const { return fmaxf(a, b); } };

__global__ void finalize_kernel(const int* __restrict__ mask, float* __restrict__ out) {
    __shared__ float sb_min[32];
    __shared__ float rbuf[32];
    __shared__ float smax[NB_HALF];
    __shared__ float sinvz[NB_HALF];

    int tid = threadIdx.x;
    int lane = tid & 31, wid = tid >> 5;

    {
        int b = wid;
        float mn = CUDART_INF_F;
        for (int t = lane; t < T_PER_B; t += 32) {
            int gr = b * T_PER_B + t;
            if (mask[gr] > 0) mn = fminf(mn, dec_f(g_rowmax[gr]));
        }
        #pragma unroll
        for (int o = 16; o; o >>= 1) mn = fminf(mn, __shfl_down_sync(0xffffffffu, mn, o));
        if (lane == 0) sb_min[b] = mn;
    }
    __syncthreads();

    for (int b = 0; b < NB_HALF; b++) {
        float mx = -CUDART_INF_F;
        for (int n = tid; n < NBLK; n += blockDim.x) mx = fmaxf(mx, g_s[b * NBLK + n]);
        mx = block_reduce(mx, OpMax(), -CUDART_INF_F, rbuf);
        if (tid == 0) smax[b] = mx;
        float se = 0.0f;
        for (int n = tid; n < NBLK; n += blockDim.x) se += expf(g_s[b * NBLK + n] - mx);
        se = block_reduce(se, OpSum(), 0.0f, rbuf);
        if (tid == 0) sinvz[b] = 1.0f / se;
        __syncthreads();
    }

    float usq = 0.0f;
    for (int n = tid; n < NBLK; n += blockDim.x) {
        float tmp = 0.0f;
        #pragma unroll
        for (int b = 0; b < NB_HALF; b++)
            tmp += expf(g_s[b * NBLK + n] - smax[b]) * sinvz[b];
        tmp *= (1.0f / (float)NB_HALF);
        usq += tmp * tmp;
    }
    usq = block_reduce(usq, OpSum(), 0.0f, rbuf);

    if (tid == 0) {
        float mean_min = 0.0f, mean_ab = 0.0f;
        for (int b = 0; b < NB_HALF; b++) { mean_min += sb_min[b]; mean_ab += sb_min[NB_HALF + b]; }
        mean_min *= (1.0f / (float)NB_HALF);
        mean_ab  *= (1.0f / (float)NB_HALF);
        out[0] = 0.2f * sqrtf(g_div);
        out[1] = 2.0f - mean_min + mean_ab;
        out[2] = 0.5f * sqrtf(usq);
    }
}

// ---------------- launch ----------------
extern "C" void kernel_launch(void* const* d_in, const int* in_sizes, int n_in,
                              void* d_out, int out_size) {
    const float* x = nullptr;
    const int*   mask = nullptr;
    const float* w = nullptr;
    for (int i = 0; i < n_in; i++) {
        if (in_sizes[i] == NROWS * DIMK)      x = (const float*)d_in[i];
        else if (in_sizes[i] == NROWS)        mask = (const int*)d_in[i];
        else if (in_sizes[i] == NBLK * DIMK)  w = (const float*)d_in[i];
    }
    float* out = (float*)d_out;

    float* invx_ptr; cudaGetSymbolAddress((void**)&invx_ptr, g_invx);
    float* invw_ptr; cudaGetSymbolAddress((void**)&invw_ptr, g_invw);

    cudaFuncSetAttribute(mma_gemm_kernel<true>,  cudaFuncAttributeMaxDynamicSharedMemorySize, SMEM_BYTES);
    cudaFuncSetAttribute(mma_gemm_kernel<false>, cudaFuncAttributeMaxDynamicSharedMemorySize, SMEM_BYTES);

    init_kernel<<<(NROWS + 255) / 256, 256>>>();
    row_invnorm_kernel<<<NROWS, 256>>>(x, invx_ptr);
    row_invnorm_kernel<<<NBLK, 256>>>(w, invw_ptr);
    mma_gemm_kernel<true><<<dim3(16, 256), NTH, SMEM_BYTES>>>(x, w, mask);
    mma_gemm_kernel<false><<<dim3(16, 16), NTH, SMEM_BYTES>>>(w, w, nullptr);
    finalize_kernel<<<1, 1024>>>(mask, out);
}

// round 6
// speedup vs baseline: 3.5220x; 1.0483x over previous
#include <cuda_runtime.h>
#include <math_constants.h>
#include <cstdint>

#define DIMK   2048
#define NBLK   2000
#define NROWS  32768        // 32 * 1024
#define T_PER_B 1024
#define NB_HALF 16

#define BM 128
#define BN 128
#define BK 32
#define NITER (DIMK / BK)    // 64
#define NSTG 3               // cp.async pipeline depth
#define NTH 256

#define TILE_FLOATS (BM * BK)            // 4096 floats = 16KB
#define TILE_BYTES  (TILE_FLOATS * 4)
#define B_REGION    (NSTG * TILE_FLOATS) // float offset of B tiles
#define EPIL_OFF    (2 * NSTG * TILE_FLOATS) // 24576
#define SMEM_FLOATS (EPIL_OFF + 1024)
#define SMEM_BYTES  (SMEM_FLOATS * 4)    // 102400 -> 2 CTAs/SM

// ---------------- device scratch ----------------
__device__ float        g_invx[NROWS];
__device__ float        g_invw[NBLK];
__device__ unsigned int g_rowmax[NROWS];
__device__ float        g_s[NB_HALF * NBLK];
__device__ float        g_div;

// ---------------- helpers ----------------
__device__ __forceinline__ unsigned int enc_f(float f) {
    unsigned int u = __float_as_uint(f);
    return (u & 0x80000000u) ? ~u : (u | 0x80000000u);
}
__device__ __forceinline__ float dec_f(unsigned int u) {
    unsigned int b = (u & 0x80000000u) ? (u ^ 0x80000000u) : ~u;
    return __uint_as_float(b);
}
__device__ __forceinline__ uint32_t smem_u32(const void* p) {
    uint32_t a;
    asm("{ .reg .u64 t; cvta.to.shared.u64 t, %1; cvt.u32.u64 %0, t; }" : "=r"(a) : "l"(p));
    return a;
}
__device__ __forceinline__ void cp16(uint32_t dst, const float* src, uint32_t sz) {
    asm volatile("cp.async.cg.shared.global [%0], [%1], 16, %2;"
                 :: "r"(dst), "l"(src), "r"(sz) : "memory");
}
#define CP_COMMIT() asm volatile("cp.async.commit_group;" ::: "memory")
#define CP_WAIT1()  asm volatile("cp.async.wait_group 1;" ::: "memory")
#define CP_WAIT0()  asm volatile("cp.async.wait_group 0;" ::: "memory")

// raw-fp32-operand tf32 mma (HW truncates mantissa)
__device__ __forceinline__ void mma_tf32(float* d,
        float a0, float a1, float a2, float a3, float b0, float b1) {
    asm volatile(
        "mma.sync.aligned.m16n8k8.row.col.f32.tf32.tf32.f32 "
        "{%0,%1,%2,%3}, {%4,%5,%6,%7}, {%8,%9}, {%0,%1,%2,%3};"
        : "+f"(d[0]), "+f"(d[1]), "+f"(d[2]), "+f"(d[3])
        : "r"(__float_as_uint(a0)), "r"(__float_as_uint(a1)),
          "r"(__float_as_uint(a2)), "r"(__float_as_uint(a3)),
          "r"(__float_as_uint(b0)), "r"(__float_as_uint(b1)));
}

// ---------------- init ----------------
__global__ void init_kernel() {
    int i = blockIdx.x * blockDim.x + threadIdx.x;
    if (i < NB_HALF * NBLK) g_s[i] = 0.0f;
    if (i < NROWS)          g_rowmax[i] = 0u;
    if (i == 0)             g_div = 0.0f;
}

// ---------------- per-row inverse L2 norm ----------------
__global__ void row_invnorm_kernel(const float* __restrict__ X, float* __restrict__ out) {
    int r = blockIdx.x;
    const float4* xp = (const float4*)(X + (size_t)r * DIMK);
    float ss = 0.0f;
    for (int i = threadIdx.x; i < DIMK / 4; i += blockDim.x) {
        float4 v = xp[i];
        ss += v.x * v.x + v.y * v.y + v.z * v.z + v.w * v.w;
    }
    __shared__ float sm[32];
    int lane = threadIdx.x & 31, wid = threadIdx.x >> 5;
    #pragma unroll
    for (int o = 16; o; o >>= 1) ss += __shfl_down_sync(0xffffffffu, ss, o);
    if (lane == 0) sm[wid] = ss;
    __syncthreads();
    if (wid == 0) {
        float v = (lane < (int)(blockDim.x >> 5)) ? sm[lane] : 0.0f;
        #pragma unroll
        for (int o = 16; o; o >>= 1) v += __shfl_down_sync(0xffffffffu, v, o);
        if (lane == 0) out[r] = 1.0f / fmaxf(sqrtf(v), 1e-12f);
    }
}

// ---------------- tf32 mma.sync GEMM, cp.async 3-stage, unrolled buffers ----------------
// smem tile: row-major, 32 floats/row (128B = 8 granules of 16B).
// Granule swizzle: phys_q = q ^ fxor(r), fxor(r) = (r&3) ^ ((r&1)<<2).
template <bool IS_ATT>
__global__ __launch_bounds__(NTH, 2)
void mma_gemm_kernel(const float* __restrict__ A, const float* __restrict__ B,
                     const int* __restrict__ mask, int row0, int col0, float dupw) {
    extern __shared__ float smf[];
    float* rowfac_s = smf + EPIL_OFF;     // [128]
    float* invw_s   = rowfac_s + 128;     // [128]
    float* bias_s   = invw_s + 128;       // [128]
    float* csum_s   = bias_s + 128;       // [128]
    float* redm     = csum_s + 128;       // [128][4]

    const int tid  = threadIdx.x;
    const int lane = tid & 31, wid = tid >> 5;
    const int wm = wid >> 2, wn = wid & 3;
    const int g = lane >> 2, c = lane & 3;
    const bool fh = IS_ATT && (row0 < NROWS / 2);

    if (IS_ATT && tid < 128) {
        int gr = row0 + tid;
        rowfac_s[tid] = g_invx[gr] * (float)mask[gr];
        int n = col0 + tid;
        bool v = n < NBLK;
        invw_s[tid] = v ? g_invw[n] : 0.0f;
        bias_s[tid] = v ? 0.0f : -CUDART_INF_F;
        csum_s[tid] = 0.0f;
    }

    // ---- cp.async setup ----
    const int r_ld = tid >> 1;
    const int h    = tid & 1;
    const int fx   = (r_ld & 3) ^ ((r_ld & 1) << 2);
    const uint32_t sbase = smem_u32(smf);
    uint32_t a_dst[4], b_dst[4];
    #pragma unroll
    for (int j = 0; j < 4; j++) {
        int q = h * 4 + j;
        uint32_t off = (uint32_t)r_ld * 128u + (uint32_t)((q ^ fx) * 16);
        a_dst[j] = sbase + off;
        b_dst[j] = sbase + (uint32_t)(B_REGION * 4) + off;
    }
    const bool a_ok = IS_ATT || (row0 + r_ld) < NBLK;
    const bool b_ok = (col0 + r_ld) < NBLK;
    const uint32_t a_sz = a_ok ? 16u : 0u;
    const uint32_t b_sz = b_ok ? 16u : 0u;
    const float* a_src = A + (size_t)(a_ok ? (row0 + r_ld) : 0) * DIMK + h * 16;
    const float* b_src = B + (size_t)(b_ok ? (col0 + r_ld) : 0) * DIMK + h * 16;

    // ---- accumulators ----
    float d[4][4][4];
    #pragma unroll
    for (int i = 0; i < 4; i++)
        #pragma unroll
        for (int j = 0; j < 4; j++)
            #pragma unroll
            for (int r = 0; r < 4; r++) d[i][j][r] = 0.0f;

    const int p4  = (c ^ ((g & 3) ^ ((g & 1) << 2))) * 4;  // float offset of granule
    const int p4x = p4 ^ 16;

    // fragment base pointers (buffer 0); other buffers reached via constant imm
    const float* pA  = smf + (wm * 64 + g) * 32 + p4;
    const float* pAx = smf + (wm * 64 + g) * 32 + p4x;
    const float* pB  = smf + B_REGION + (wn * 32 + g) * 32 + p4;
    const float* pBx = smf + B_REGION + (wn * 32 + g) * 32 + p4x;

    auto compute = [&](const int bufc) {
        const float* Ab  = pA  + bufc * TILE_FLOATS;
        const float* Abx = pAx + bufc * TILE_FLOATS;
        const float* Bb  = pB  + bufc * TILE_FLOATS;
        const float* Bbx = pBx + bufc * TILE_FLOATS;
        float4 bl[4], bh[4];
        #pragma unroll
        for (int jn = 0; jn < 4; jn++) {
            bl[jn] = *(const float4*)(Bb  + jn * 256);
            bh[jn] = *(const float4*)(Bbx + jn * 256);
        }
        #pragma unroll
        for (int i = 0; i < 4; i++) {
            float4 al0 = *(const float4*)(Ab  + i * 512);
            float4 ah0 = *(const float4*)(Abx + i * 512);
            float4 al1 = *(const float4*)(Ab  + i * 512 + 256);
            float4 ah1 = *(const float4*)(Abx + i * 512 + 256);
            #pragma unroll
            for (int jn = 0; jn < 4; jn++) {
                mma_tf32(d[i][jn], al0.x, al1.x, al0.y, al1.y, bl[jn].x, bl[jn].y);
                mma_tf32(d[i][jn], al0.z, al1.z, al0.w, al1.w, bl[jn].z, bl[jn].w);
                mma_tf32(d[i][jn], ah0.x, ah1.x, ah0.y, ah1.y, bh[jn].x, bh[jn].y);
                mma_tf32(d[i][jn], ah0.z, ah1.z, ah0.w, ah1.w, bh[jn].z, bh[jn].w);
            }
        }
    };

    // running gmem pointers for prefetch (start at stage 2)
    const float* a_run = a_src + 2 * BK;
    const float* b_run = b_src + 2 * BK;

    auto step = [&](const int bufc, const bool do_load) {
        CP_WAIT1();
        __syncthreads();
        if (do_load) {
            const uint32_t ldoff = (uint32_t)(((bufc + 2) % NSTG) * TILE_BYTES);
            #pragma unroll
            for (int j = 0; j < 4; j++) {
                cp16(a_dst[j] + ldoff, a_run + j * 4, a_sz);
                cp16(b_dst[j] + ldoff, b_run + j * 4, b_sz);
            }
            a_run += BK;
            b_run += BK;
        }
        CP_COMMIT();
        compute(bufc);
    };

    // ---- preload stages 0,1 ----
    #pragma unroll
    for (int j = 0; j < 4; j++) {
        cp16(a_dst[j], a_src + j * 4, a_sz);
        cp16(b_dst[j], b_src + j * 4, b_sz);
    }
    CP_COMMIT();
    #pragma unroll
    for (int j = 0; j < 4; j++) {
        cp16(a_dst[j] + TILE_BYTES, a_src + BK + j * 4, a_sz);
        cp16(b_dst[j] + TILE_BYTES, b_src + BK + j * 4, b_sz);
    }
    CP_COMMIT();

    // stages 0..59 in triples, tail 60..63
    #pragma unroll 1
    for (int t = 0; t < 20; t++) {
        step(0, true);
        step(1, true);
        step(2, true);
    }
    step(0, true);   // s=60, loads 62
    step(1, true);   // s=61, loads 63
    step(2, false);  // s=62
    step(0, false);  // s=63
    CP_WAIT0();

    // ---------------- epilogue ----------------
    if (IS_ATT) {
        #pragma unroll
        for (int i = 0; i < 4; i++) {
            float m0 = -CUDART_INF_F, m1 = -CUDART_INF_F;
            #pragma unroll
            for (int jn = 0; jn < 4; jn++) {
                int nb = wn * 32 + jn * 8 + 2 * c;
                float iw0 = invw_s[nb], iw1 = invw_s[nb + 1];
                float bz0 = bias_s[nb], bz1 = bias_s[nb + 1];
                m0 = fmaxf(m0, fmaxf(fmaf(d[i][jn][0], iw0, bz0), fmaf(d[i][jn][1], iw1, bz1)));
                m1 = fmaxf(m1, fmaxf(fmaf(d[i][jn][2], iw0, bz0), fmaf(d[i][jn][3], iw1, bz1)));
            }
            m0 = fmaxf(m0, __shfl_xor_sync(0xffffffffu, m0, 1));
            m0 = fmaxf(m0, __shfl_xor_sync(0xffffffffu, m0, 2));
            m1 = fmaxf(m1, __shfl_xor_sync(0xffffffffu, m1, 1));
            m1 = fmaxf(m1, __shfl_xor_sync(0xffffffffu, m1, 2));
            if (c == 0) {
                redm[(wm * 64 + i * 16 + g) * 4 + wn]     = m0;
                redm[(wm * 64 + i * 16 + g + 8) * 4 + wn] = m1;
            }
        }
        if (fh) {
            float cs[4][2];
            #pragma unroll
            for (int jn = 0; jn < 4; jn++) { cs[jn][0] = 0.0f; cs[jn][1] = 0.0f; }
            #pragma unroll
            for (int i = 0; i < 4; i++) {
                float rf0 = rowfac_s[wm * 64 + i * 16 + g];
                float rf1 = rowfac_s[wm * 64 + i * 16 + g + 8];
                #pragma unroll
                for (int jn = 0; jn < 4; jn++) {
                    cs[jn][0] += d[i][jn][0] * rf0 + d[i][jn][2] * rf1;
                    cs[jn][1] += d[i][jn][1] * rf0 + d[i][jn][3] * rf1;
                }
            }
            #pragma unroll
            for (int jn = 0; jn < 4; jn++) {
                #pragma unroll
                for (int u = 0; u < 2; u++) {
                    float s = cs[jn][u];
                    s += __shfl_xor_sync(0xffffffffu, s, 4);
                    s += __shfl_xor_sync(0xffffffffu, s, 8);
                    s += __shfl_xor_sync(0xffffffffu, s, 16);
                    if (lane < 4) atomicAdd(&csum_s[wn * 32 + jn * 8 + 2 * c + u], s);
                }
            }
        }
        __syncthreads();
        if (tid < 128) {
            float m = fmaxf(fmaxf(redm[tid * 4 + 0], redm[tid * 4 + 1]),
                            fmaxf(redm[tid * 4 + 2], redm[tid * 4 + 3]));
            int gr = row0 + tid;
            atomicMax(&g_rowmax[gr], enc_f(m * g_invx[gr]));
        }
        if (fh && tid < 128) {
            int n = col0 + tid;
            if (n < NBLK) {
                int b = row0 >> 10;
                atomicAdd(&g_s[b * NBLK + n], csum_s[tid] * invw_s[tid]);
            }
        }
    } else {
        float acc = 0.0f;
        #pragma unroll
        for (int i = 0; i < 4; i++) {
            int m0 = row0 + wm * 64 + i * 16 + g;
            #pragma unroll
            for (int jn = 0; jn < 4; jn++) {
                int n0 = col0 + wn * 32 + jn * 8 + 2 * c;
                float e;
                e = d[i][jn][0] - ((m0 == n0     && m0 < NBLK) ? 1.0f : 0.0f); acc += e * e;
                e = d[i][jn][1] - ((m0 == n0 + 1 && m0 < NBLK) ? 1.0f : 0.0f); acc += e * e;
                e = d[i][jn][2] - ((m0 + 8 == n0     && m0 + 8 < NBLK) ? 1.0f : 0.0f); acc += e * e;
                e = d[i][jn][3] - ((m0 + 8 == n0 + 1 && m0 + 8 < NBLK) ? 1.0f : 0.0f); acc += e * e;
            }
        }
        acc *= dupw;   // 2.0 for off-diagonal tiles (symmetric gram), 1.0 on diagonal
        #pragma unroll
        for (int o = 16; o; o >>= 1) acc += __shfl_xor_sync(0xffffffffu, acc, o);
        if (lane == 0) csum_s[wid] = acc;
        __syncthreads();
        if (tid == 0) {
            float t = 0.0f;
            #pragma unroll
            for (int w = 0; w < 8; w++) t += csum_s[w];
            atomicAdd(&g_div, t);
        }
    }
}

// wrappers: att uses 2D grid; div uses triangular 1D grid
__global__ void dummy_unused() {}

template <bool IS_ATT>
__global__ __launch_bounds__(NTH, 2)
void att_entry(const float* __restrict__ A, const float* __restrict__ B,
               const int* __restrict__ mask);

// att entry: map blockIdx -> (row0, col0)
__global__ __launch_bounds__(NTH, 2)
void att_kernel(const float* __restrict__ A, const float* __restrict__ B,
                const int* __restrict__ mask);

// Use direct launches of mma_gemm_kernel with computed coords via a thin device-side
// decode: implement as separate kernels calling the body is not possible; instead
// replicate via an index-decoding prologue in two small wrappers below.

// --- att wrapper: grid (16, 256) ---
__global__ __launch_bounds__(NTH, 2)
void att_gemm(const float* __restrict__ A, const float* __restrict__ B,
              const int* __restrict__ mask);

// Simpler: just launch mma_gemm_kernel directly with row0/col0 derived inside.
// To keep one body, we pass row0/col0 as kernel args from per-tile grids is not
// possible for 2D grids; so make tiny trampoline kernels below.

template <bool IS_ATT>
__device__ __forceinline__ void run_tile(const float*, const float*, const int*, int, int, float);

// ---------------- finalize ----------------
template <typename Op>
__device__ __forceinline__ float block_reduce(float v, Op op, float ident, float* sbuf) {
    __syncthreads();
    int tid = threadIdx.x, lane = tid & 31, wid = tid >> 5;
    #pragma unroll
    for (int o = 16; o; o >>= 1) v = op(v, __shfl_down_sync(0xffffffffu, v, o));
    if (lane == 0) sbuf[wid] = v;
    __syncthreads();
    int nw = blockDim.x >> 5;
    if (wid == 0) {
        float w = (lane < nw) ? sbuf[lane] : ident;
        #pragma unroll
        for (int o = 16; o; o >>= 1) w = op(w, __shfl_down_sync(0xffffffffu, w, o));
        if (lane == 0) sbuf[0] = w;
    }
    __syncthreads();
    return sbuf[0];
}
struct OpSum { __device__ float operator()(float a, float b) const { return a + b; } };
struct OpMax { __device__ float operator()(float a, float b) const { return fmaxf(a, b); } };

__global__ void finalize_kernel(const int* __restrict__ mask, float* __restrict__ out) {
    __shared__ float sb_min[32];
    __shared__ float rbuf[32];
    __shared__ float smax[NB_HALF];
    __shared__ float sinvz[NB_HALF];

    int tid = threadIdx.x;
    int lane = tid & 31, wid = tid >> 5;

    {
        int b = wid;
        float mn = CUDART_INF_F;
        for (int t = lane; t < T_PER_B; t += 32) {
            int gr = b * T_PER_B + t;
            if (mask[gr] > 0) mn = fminf(mn, dec_f(g_rowmax[gr]));
        }
        #pragma unroll
        for (int o = 16; o; o >>= 1) mn = fminf(mn, __shfl_down_sync(0xffffffffu, mn, o));
        if (lane == 0) sb_min[b] = mn;
    }
    __syncthreads();

    for (int b = 0; b < NB_HALF; b++) {
        float mx = -CUDART_INF_F;
        for (int n = tid; n < NBLK; n += blockDim.x) mx = fmaxf(mx, g_s[b * NBLK + n]);
        mx = block_reduce(mx, OpMax(), -CUDART_INF_F, rbuf);
        if (tid == 0) smax[b] = mx;
        float se = 0.0f;
        for (int n = tid; n < NBLK; n += blockDim.x) se += expf(g_s[b * NBLK + n] - mx);
        se = block_reduce(se, OpSum(), 0.0f, rbuf);
        if (tid == 0) sinvz[b] = 1.0f / se;
        __syncthreads();
    }

    float usq = 0.0f;
    for (int n = tid; n < NBLK; n += blockDim.x) {
        float tmp = 0.0f;
        #pragma unroll
        for (int b = 0; b < NB_HALF; b++)
            tmp += expf(g_s[b * NBLK + n] - smax[b]) * sinvz[b];
        tmp *= (1.0f / (float)NB_HALF);
        usq += tmp * tmp;
    }
    usq = block_reduce(usq, OpSum(), 0.0f, rbuf);

    if (tid == 0) {
        float mean_min = 0.0f, mean_ab = 0.0f;
        for (int b = 0; b < NB_HALF; b++) { mean_min += sb_min[b]; mean_ab += sb_min[NB_HALF + b]; }
        mean_min *= (1.0f / (float)NB_HALF);
        mean_ab  *= (1.0f / (float)NB_HALF);
        out[0] = 0.2f * sqrtf(g_div);
        out[1] = 2.0f - mean_min + mean_ab;
        out[2] = 0.5f * sqrtf(usq);
    }
}

// ---------------- trampolines ----------------
// att: grid (16, 256) -> tile coords
__global__ __launch_bounds__(NTH, 2)
void att_trampoline(const float* __restrict__ A, const float* __restrict__ B,
                    const int* __restrict__ mask);
// div: triangular 1D grid of 136 -> (ti <= tj)
__global__ __launch_bounds__(NTH, 2)
void div_trampoline(const float* __restrict__ W);

// NOTE: CUDA cannot "call" another __global__; mma_gemm_kernel is launched directly
// with (row0, col0, dupw) passed as arguments using flattened grids.

extern "C" void kernel_launch(void* const* d_in, const int* in_sizes, int n_in,
                              void* d_out, int out_size);

// att launcher uses mma_gemm_kernel<true> with blockIdx decode done on host side?
// -> grid must carry coords; use blockIdx inside a thin wrapper via template arg trick:

template <bool IS_ATT>
__global__ __launch_bounds__(NTH, 2)
void gemm_entry(const float* __restrict__ A, const float* __restrict__ B,
                const int* __restrict__ mask) {
    // decode tile coords
    int row0, col0;
    float dupw = 1.0f;
    if (IS_ATT) {
        row0 = blockIdx.y * BM;
        col0 = blockIdx.x * BN;
    } else {
        int bid = blockIdx.x;
        int ti = 0, rem = bid;
        while (rem >= 16 - ti) { rem -= 16 - ti; ti++; }
        int tj = ti + rem;
        row0 = ti * BM;
        col0 = tj * BN;
        dupw = (ti == tj) ? 1.0f : 2.0f;
    }
    // inline the whole body by tail-calling the __device__-ified worker:
    // (mma_gemm_kernel's body was written as a kernel; replicate via macro-include)
    // -- body inlined below by calling device function --
    extern __shared__ float smf_[];
    (void)smf_;
    // delegate
    void ENPM_body(const float*, const float*, const int*, int, int, float);
    // placeholder; real dispatch below
}

// ---- actual implementation: make the worker a __device__ function ----
// (Re-declare cleanly: the kernel above named mma_gemm_kernel is unused; the
//  real entry points are gemm_run<IS_ATT> below.)

template <bool IS_ATT>
__device__ void gemm_body(const float* __restrict__ A, const float* __restrict__ B,
                          const int* __restrict__ mask, int row0, int col0, float dupw);

template <bool IS_ATT>
__global__ __launch_bounds__(NTH, 2)
void gemm_run(const float* __restrict__ A, const float* __restrict__ B,
              const int* __restrict__ mask) {
    int row0, col0;
    float dupw = 1.0f;
    if (IS_ATT) {
        row0 = blockIdx.y * BM;
        col0 = blockIdx.x * BN;
    } else {
        int bid = blockIdx.x;
        int ti = 0, rem = bid;
        while (rem >= 16 - ti) { rem -= 16 - ti; ti++; }
        int tj = ti + rem;
        row0 = ti * BM;
        col0 = tj * BN;
        dupw = (ti == tj) ? 1.0f : 2.0f;
    }
    gemm_body<IS_ATT>(A, B, mask, row0, col0, dupw);
}

template <bool IS_ATT>
__device__ void gemm_body(const float* __restrict__ A, const float* __restrict__ B,
                          const int* __restrict__ mask, int row0, int col0, float dupw) {
    extern __shared__ float smf[];
    float* rowfac_s = smf + EPIL_OFF;
    float* invw_s   = rowfac_s + 128;
    float* bias_s   = invw_s + 128;
    float* csum_s   = bias_s + 128;
    float* redm     = csum_s + 128;

    const int tid  = threadIdx.x;
    const int lane = tid & 31, wid = tid >> 5;
    const int wm = wid >> 2, wn = wid & 3;
    const int g = lane >> 2, c = lane & 3;
    const bool fh = IS_ATT && (row0 < NROWS / 2);

    if (IS_ATT && tid < 128) {
        int gr = row0 + tid;
        rowfac_s[tid] = g_invx[gr] * (float)mask[gr];
        int n = col0 + tid;
        bool v = n < NBLK;
        invw_s[tid] = v ? g_invw[n] : 0.0f;
        bias_s[tid] = v ? 0.0f : -CUDART_INF_F;
        csum_s[tid] = 0.0f;
    }

    const int r_ld = tid >> 1;
    const int h    = tid & 1;
    const int fx   = (r_ld & 3) ^ ((r_ld & 1) << 2);
    const uint32_t sbase = smem_u32(smf);
    uint32_t a_dst[4], b_dst[4];
    #pragma unroll
    for (int j = 0; j < 4; j++) {
        int q = h * 4 + j;
        uint32_t off = (uint32_t)r_ld * 128u + (uint32_t)((q ^ fx) * 16);
        a_dst[j] = sbase + off;
        b_dst[j] = sbase + (uint32_t)(B_REGION * 4) + off;
    }
    const bool a_ok = IS_ATT || (row0 + r_ld) < NBLK;
    const bool b_ok = (col0 + r_ld) < NBLK;
    const uint32_t a_sz = a_ok ? 16u : 0u;
    const uint32_t b_sz = b_ok ? 16u : 0u;
    const float* a_src = A + (size_t)(a_ok ? (row0 + r_ld) : 0) * DIMK + h * 16;
    const float* b_src = B + (size_t)(b_ok ? (col0 + r_ld) : 0) * DIMK + h * 16;

    float d[4][4][4];
    #pragma unroll
    for (int i = 0; i < 4; i++)
        #pragma unroll
        for (int j = 0; j < 4; j++)
            #pragma unroll
            for (int r = 0; r < 4; r++) d[i][j][r] = 0.0f;

    const int p4  = (c ^ ((g & 3) ^ ((g & 1) << 2))) * 4;
    const int p4x = p4 ^ 16;

    const float* pA  = smf + (wm * 64 + g) * 32 + p4;
    const float* pAx = smf + (wm * 64 + g) * 32 + p4x;
    const float* pB  = smf + B_REGION + (wn * 32 + g) * 32 + p4;
    const float* pBx = smf + B_REGION + (wn * 32 + g) * 32 + p4x;

    const float* a_run = a_src + 2 * BK;
    const float* b_run = b_src + 2 * BK;

    auto compute = [&](const int bufc) {
        const float* Ab  = pA  + bufc * TILE_FLOATS;
        const float* Abx = pAx + bufc * TILE_FLOATS;
        const float* Bb  = pB  + bufc * TILE_FLOATS;
        const float* Bbx = pBx + bufc * TILE_FLOATS;
        float4 bl[4], bh[4];
        #pragma unroll
        for (int jn = 0; jn < 4; jn++) {
            bl[jn] = *(const float4*)(Bb  + jn * 256);
            bh[jn] = *(const float4*)(Bbx + jn * 256);
        }
        #pragma unroll
        for (int i = 0; i < 4; i++) {
            float4 al0 = *(const float4*)(Ab  + i * 512);
            float4 ah0 = *(const float4*)(Abx + i * 512);
            float4 al1 = *(const float4*)(Ab  + i * 512 + 256);
            float4 ah1 = *(const float4*)(Abx + i * 512 + 256);
            #pragma unroll
            for (int jn = 0; jn < 4; jn++) {
                mma_tf32(d[i][jn], al0.x, al1.x, al0.y, al1.y, bl[jn].x, bl[jn].y);
                mma_tf32(d[i][jn], al0.z, al1.z, al0.w, al1.w, bl[jn].z, bl[jn].w);
                mma_tf32(d[i][jn], ah0.x, ah1.x, ah0.y, ah1.y, bh[jn].x, bh[jn].y);
                mma_tf32(d[i][jn], ah0.z, ah1.z, ah0.w, ah1.w, bh[jn].z, bh[jn].w);
            }
        }
    };

    auto step = [&](const int bufc, const bool do_load) {
        CP_WAIT1();
        __syncthreads();
        if (do_load) {
            const uint32_t ldoff = (uint32_t)(((bufc + 2) % NSTG) * TILE_BYTES);
            #pragma unroll
            for (int j = 0; j < 4; j++) {
                cp16(a_dst[j] + ldoff, a_run + j * 4, a_sz);
                cp16(b_dst[j] + ldoff, b_run + j * 4, b_sz);
            }
            a_run += BK;
            b_run += BK;
        }
        CP_COMMIT();
        compute(bufc);
    };

    #pragma unroll
    for (int j = 0; j < 4; j++) {
        cp16(a_dst[j], a_src + j * 4, a_sz);
        cp16(b_dst[j], b_src + j * 4, b_sz);
    }
    CP_COMMIT();
    #pragma unroll
    for (int j = 0; j < 4; j++) {
        cp16(a_dst[j] + TILE_BYTES, a_src + BK + j * 4, a_sz);
        cp16(b_dst[j] + TILE_BYTES, b_src + BK + j * 4, b_sz);
    }
    CP_COMMIT();

    #pragma unroll 1
    for (int t = 0; t < 20; t++) {
        step(0, true);
        step(1, true);
        step(2, true);
    }
    step(0, true);
    step(1, true);
    step(2, false);
    step(0, false);
    CP_WAIT0();

    if (IS_ATT) {
        #pragma unroll
        for (int i = 0; i < 4; i++) {
            float m0 = -CUDART_INF_F, m1 = -CUDART_INF_F;
            #pragma unroll
            for (int jn = 0; jn < 4; jn++) {
                int nb = wn * 32 + jn * 8 + 2 * c;
                float iw0 = invw_s[nb], iw1 = invw_s[nb + 1];
                float bz0 = bias_s[nb], bz1 = bias_s[nb + 1];
                m0 = fmaxf(m0, fmaxf(fmaf(d[i][jn][0], iw0, bz0), fmaf(d[i][jn][1], iw1, bz1)));
                m1 = fmaxf(m1, fmaxf(fmaf(d[i][jn][2], iw0, bz0), fmaf(d[i][jn][3], iw1, bz1)));
            }
            m0 = fmaxf(m0, __shfl_xor_sync(0xffffffffu, m0, 1));
            m0 = fmaxf(m0, __shfl_xor_sync(0xffffffffu, m0, 2));
            m1 = fmaxf(m1, __shfl_xor_sync(0xffffffffu, m1, 1));
            m1 = fmaxf(m1, __shfl_xor_sync(0xffffffffu, m1, 2));
            if (c == 0) {
                redm[(wm * 64 + i * 16 + g) * 4 + wn]     = m0;
                redm[(wm * 64 + i * 16 + g + 8) * 4 + wn] = m1;
            }
        }
        if (fh) {
            float cs[4][2];
            #pragma unroll
            for (int jn = 0; jn < 4; jn++) { cs[jn][0] = 0.0f; cs[jn][1] = 0.0f; }
            #pragma unroll
            for (int i = 0; i < 4; i++) {
                float rf0 = rowfac_s[wm * 64 + i * 16 + g];
                float rf1 = rowfac_s[wm * 64 + i * 16 + g + 8];
                #pragma unroll
                for (int jn = 0; jn < 4; jn++) {
                    cs[jn][0] += d[i][jn][0] * rf0 + d[i][jn][2] * rf1;
                    cs[jn][1] += d[i][jn][1] * rf0 + d[i][jn][3] * rf1;
                }
            }
            #pragma unroll
            for (int jn = 0; jn < 4; jn++) {
                #pragma unroll
                for (int u = 0; u < 2; u++) {
                    float s = cs[jn][u];
                    s += __shfl_xor_sync(0xffffffffu, s, 4);
                    s += __shfl_xor_sync(0xffffffffu, s, 8);
                    s += __shfl_xor_sync(0xffffffffu, s, 16);
                    if (lane < 4) atomicAdd(&csum_s[wn * 32 + jn * 8 + 2 * c + u], s);
                }
            }
        }
        __syncthreads();
        if (tid < 128) {
            float m = fmaxf(fmaxf(redm[tid * 4 + 0], redm[tid * 4 + 1]),
                            fmaxf(redm[tid * 4 + 2], redm[tid * 4 + 3]));
            int gr = row0 + tid;
            atomicMax(&g_rowmax[gr], enc_f(m * g_invx[gr]));
        }
        if (fh && tid < 128) {
            int n = col0 + tid;
            if (n < NBLK) {
                int b = row0 >> 10;
                atomicAdd(&g_s[b * NBLK + n], csum_s[tid] * invw_s[tid]);
            }
        }
    } else {
        float acc = 0.0f;
        #pragma unroll
        for (int i = 0; i < 4; i++) {
            int m0 = row0 + wm * 64 + i * 16 + g;
            #pragma unroll
            for (int jn = 0; jn < 4; jn++) {
                int n0 = col0 + wn * 32 + jn * 8 + 2 * c;
                float e;
                e = d[i][jn][0] - ((m0 == n0     && m0 < NBLK) ? 1.0f : 0.0f); acc += e * e;
                e = d[i][jn][1] - ((m0 == n0 + 1 && m0 < NBLK) ? 1.0f : 0.0f); acc += e * e;
                e = d[i][jn][2] - ((m0 + 8 == n0     && m0 + 8 < NBLK) ? 1.0f : 0.0f); acc += e * e;
                e = d[i][jn][3] - ((m0 + 8 == n0 + 1 && m0 + 8 < NBLK) ? 1.0f : 0.0f); acc += e * e;
            }
        }
        acc *= dupw;
        #pragma unroll
        for (int o = 16; o; o >>= 1) acc += __shfl_xor_sync(0xffffffffu, acc, o);
        if (lane == 0) csum_s[wid] = acc;
        __syncthreads();
        if (tid == 0) {
            float t = 0.0f;
            #pragma unroll
            for (int w = 0; w < 8; w++) t += csum_s[w];
            atomicAdd(&g_div, t);
        }
    }
}

// ---------------- launch ----------------
extern "C" void kernel_launch(void* const* d_in, const int* in_sizes, int n_in,
                              void* d_out, int out_size) {
    const float* x = nullptr;
    const int*   mask = nullptr;
    const float* w = nullptr;
    for (int i = 0; i < n_in; i++) {
        if (in_sizes[i] == NROWS * DIMK)      x = (const float*)d_in[i];
        else if (in_sizes[i] == NROWS)        mask = (const int*)d_in[i];
        else if (in_sizes[i] == NBLK * DIMK)  w = (const float*)d_in[i];
    }
    float* out = (float*)d_out;

    float* invx_ptr; cudaGetSymbolAddress((void**)&invx_ptr, g_invx);
    float* invw_ptr; cudaGetSymbolAddress((void**)&invw_ptr, g_invw);

    cudaFuncSetAttribute(gemm_run<true>,  cudaFuncAttributeMaxDynamicSharedMemorySize, SMEM_BYTES);
    cudaFuncSetAttribute(gemm_run<false>, cudaFuncAttributeMaxDynamicSharedMemorySize, SMEM_BYTES);

    init_kernel<<<(NROWS + 255) / 256, 256>>>();
    row_invnorm_kernel<<<NROWS, 256>>>(x, invx_ptr);
    row_invnorm_kernel<<<NBLK, 256>>>(w, invw_ptr);
    gemm_run<true><<<dim3(16, 256), NTH, SMEM_BYTES>>>(x, w, mask);
    gemm_run<false><<<dim3(136, 1), NTH, SMEM_BYTES>>>(w, w, nullptr);  // upper triangle
    finalize_kernel<<<1, 1024>>>(mask, out);
}

// round 7
// speedup vs baseline: 3.5810x; 1.0168x over previous
#include <cuda_runtime.h>
#include <math_constants.h>
#include <cstdint>

#define DIMK   2048
#define NBLK   2000
#define NROWS  32768        // 32 * 1024
#define T_PER_B 1024
#define NB_HALF 16

#define BM 128
#define BN 128
#define BK 32
#define NITER (DIMK / BK)    // 64
#define NSTG 3               // cp.async pipeline depth
#define NTH 128              // 4 warps, 64x64 warp tiles

#define TILE_FLOATS (BM * BK)            // 4096 floats = 16KB
#define TILE_BYTES  (TILE_FLOATS * 4)
#define B_REGION    (NSTG * TILE_FLOATS)
#define EPIL_OFF    (2 * NSTG * TILE_FLOATS) // 24576 floats
#define SMEM_FLOATS (EPIL_OFF + 1024)
#define SMEM_BYTES  (SMEM_FLOATS * 4)    // 102400 -> 2 CTAs/SM

// ---------------- device scratch ----------------
__device__ float        g_invx[NROWS];
__device__ float        g_invw[NBLK];
__device__ unsigned int g_rowmax[NROWS];
__device__ float        g_s[NB_HALF * NBLK];
__device__ float        g_div;

// ---------------- helpers ----------------
__device__ __forceinline__ unsigned int enc_f(float f) {
    unsigned int u = __float_as_uint(f);
    return (u & 0x80000000u) ? ~u : (u | 0x80000000u);
}
__device__ __forceinline__ float dec_f(unsigned int u) {
    unsigned int b = (u & 0x80000000u) ? (u ^ 0x80000000u) : ~u;
    return __uint_as_float(b);
}
__device__ __forceinline__ uint32_t smem_u32(const void* p) {
    uint32_t a;
    asm("{ .reg .u64 t; cvta.to.shared.u64 t, %1; cvt.u32.u64 %0, t; }" : "=r"(a) : "l"(p));
    return a;
}
__device__ __forceinline__ void cp16(uint32_t dst, const float* src, uint32_t sz) {
    asm volatile("cp.async.cg.shared.global [%0], [%1], 16, %2;"
                 :: "r"(dst), "l"(src), "r"(sz) : "memory");
}
#define CP_COMMIT() asm volatile("cp.async.commit_group;" ::: "memory")
#define CP_WAIT1()  asm volatile("cp.async.wait_group 1;" ::: "memory")
#define CP_WAIT0()  asm volatile("cp.async.wait_group 0;" ::: "memory")

// raw-fp32-operand tf32 mma (HW truncates mantissa)
__device__ __forceinline__ void mma_tf32(float* d,
        float a0, float a1, float a2, float a3, float b0, float b1) {
    asm volatile(
        "mma.sync.aligned.m16n8k8.row.col.f32.tf32.tf32.f32 "
        "{%0,%1,%2,%3}, {%4,%5,%6,%7}, {%8,%9}, {%0,%1,%2,%3};"
        : "+f"(d[0]), "+f"(d[1]), "+f"(d[2]), "+f"(d[3])
        : "r"(__float_as_uint(a0)), "r"(__float_as_uint(a1)),
          "r"(__float_as_uint(a2)), "r"(__float_as_uint(a3)),
          "r"(__float_as_uint(b0)), "r"(__float_as_uint(b1)));
}

// ---------------- init ----------------
__global__ void init_kernel() {
    int i = blockIdx.x * blockDim.x + threadIdx.x;
    if (i < NB_HALF * NBLK) g_s[i] = 0.0f;
    if (i < NROWS)          g_rowmax[i] = 0u;
    if (i == 0)             g_div = 0.0f;
}

// ---------------- per-row inverse L2 norm ----------------
__global__ void row_invnorm_kernel(const float* __restrict__ X, float* __restrict__ out) {
    int r = blockIdx.x;
    const float4* xp = (const float4*)(X + (size_t)r * DIMK);
    float ss = 0.0f;
    for (int i = threadIdx.x; i < DIMK / 4; i += blockDim.x) {
        float4 v = xp[i];
        ss += v.x * v.x + v.y * v.y + v.z * v.z + v.w * v.w;
    }
    __shared__ float sm[32];
    int lane = threadIdx.x & 31, wid = threadIdx.x >> 5;
    #pragma unroll
    for (int o = 16; o; o >>= 1) ss += __shfl_down_sync(0xffffffffu, ss, o);
    if (lane == 0) sm[wid] = ss;
    __syncthreads();
    if (wid == 0) {
        float v = (lane < (int)(blockDim.x >> 5)) ? sm[lane] : 0.0f;
        #pragma unroll
        for (int o = 16; o; o >>= 1) v += __shfl_down_sync(0xffffffffu, v, o);
        if (lane == 0) out[r] = 1.0f / fmaxf(sqrtf(v), 1e-12f);
    }
}

// ---------------- tf32 mma.sync GEMM: 4 warps, 64x64 warp tiles ----------------
// smem tile: row-major, 32 floats/row. Granule swizzle:
//   phys_q = q ^ fxor(r), fxor(r) = (r&3) ^ ((r&1)<<2).
template <bool IS_ATT>
__device__ void gemm_body(const float* __restrict__ A, const float* __restrict__ B,
                          const int* __restrict__ mask, int row0, int col0, float dupw) {
    extern __shared__ float smf[];
    float* rowfac_s = smf + EPIL_OFF;     // [128]
    float* invw_s   = rowfac_s + 128;     // [128]
    float* bias_s   = invw_s + 128;       // [128]
    float* csum_s   = bias_s + 128;       // [128]
    float* redm     = csum_s + 128;       // [128][2]

    const int tid  = threadIdx.x;
    const int lane = tid & 31, wid = tid >> 5;
    const int wm = wid >> 1, wn = wid & 1;        // 2x2 warp grid
    const int g = lane >> 2, c = lane & 3;
    const bool fh = IS_ATT && (row0 < NROWS / 2);

    if (IS_ATT) {
        int gr = row0 + tid;
        rowfac_s[tid] = g_invx[gr] * (float)mask[gr];
        int n = col0 + tid;
        bool v = n < NBLK;
        invw_s[tid] = v ? g_invw[n] : 0.0f;
        bias_s[tid] = v ? 0.0f : -CUDART_INF_F;
        csum_s[tid] = 0.0f;
    }

    // ---- cp.async setup: 128 threads, 2 threads/row, 2 row-passes (0..63, 64..127) ----
    const int r_ld = tid >> 1;         // 0..63
    const int h    = tid & 1;
    const int fx   = (r_ld & 3) ^ ((r_ld & 1) << 2);   // same for r_ld+64
    const uint32_t sbase = smem_u32(smf);
    uint32_t a_dst[4], b_dst[4];
    #pragma unroll
    for (int j = 0; j < 4; j++) {
        int q = h * 4 + j;
        uint32_t off = (uint32_t)r_ld * 128u + (uint32_t)((q ^ fx) * 16);
        a_dst[j] = sbase + off;
        b_dst[j] = sbase + (uint32_t)(B_REGION * 4) + off;
    }
    const bool a_ok0 = IS_ATT || (row0 + r_ld) < NBLK;
    const bool a_ok1 = IS_ATT || (row0 + r_ld + 64) < NBLK;
    const bool b_ok0 = (col0 + r_ld) < NBLK;
    const bool b_ok1 = (col0 + r_ld + 64) < NBLK;
    const uint32_t a_sz0 = a_ok0 ? 16u : 0u;
    const uint32_t a_sz1 = a_ok1 ? 16u : 0u;
    const uint32_t b_sz0 = b_ok0 ? 16u : 0u;
    const uint32_t b_sz1 = b_ok1 ? 16u : 0u;
    const float* a_src0 = A + (size_t)(a_ok0 ? (row0 + r_ld) : 0) * DIMK + h * 16;
    const float* a_src1 = A + (size_t)(a_ok1 ? (row0 + r_ld + 64) : 0) * DIMK + h * 16;
    const float* b_src0 = B + (size_t)(b_ok0 ? (col0 + r_ld) : 0) * DIMK + h * 16;
    const float* b_src1 = B + (size_t)(b_ok1 ? (col0 + r_ld + 64) : 0) * DIMK + h * 16;

    // ---- accumulators: 4 i-chunks x 8 jn-groups x 4 ----
    float d[4][8][4];
    #pragma unroll
    for (int i = 0; i < 4; i++)
        #pragma unroll
        for (int j = 0; j < 8; j++)
            #pragma unroll
            for (int r = 0; r < 4; r++) d[i][j][r] = 0.0f;

    const int p4  = (c ^ ((g & 3) ^ ((g & 1) << 2))) * 4;
    const int p4x = p4 ^ 16;

    const float* pA  = smf + (wm * 64 + g) * 32 + p4;
    const float* pAx = smf + (wm * 64 + g) * 32 + p4x;
    const float* pB  = smf + B_REGION + (wn * 64 + g) * 32 + p4;
    const float* pBx = smf + B_REGION + (wn * 64 + g) * 32 + p4x;

    const float* a_run0 = a_src0 + 2 * BK;
    const float* a_run1 = a_src1 + 2 * BK;
    const float* b_run0 = b_src0 + 2 * BK;
    const float* b_run1 = b_src1 + 2 * BK;

    auto compute = [&](const int bufc) {
        const float* Ab  = pA  + bufc * TILE_FLOATS;
        const float* Abx = pAx + bufc * TILE_FLOATS;
        const float* Bb  = pB  + bufc * TILE_FLOATS;
        const float* Bbx = pBx + bufc * TILE_FLOATS;
        float4 bl[8], bh[8];
        #pragma unroll
        for (int jn = 0; jn < 8; jn++) {
            bl[jn] = *(const float4*)(Bb  + jn * 256);
            bh[jn] = *(const float4*)(Bbx + jn * 256);
        }
        #pragma unroll
        for (int i = 0; i < 4; i++) {
            float4 al0 = *(const float4*)(Ab  + i * 512);
            float4 ah0 = *(const float4*)(Abx + i * 512);
            float4 al1 = *(const float4*)(Ab  + i * 512 + 256);
            float4 ah1 = *(const float4*)(Abx + i * 512 + 256);
            #pragma unroll
            for (int jn = 0; jn < 8; jn++) {
                mma_tf32(d[i][jn], al0.x, al1.x, al0.y, al1.y, bl[jn].x, bl[jn].y);
                mma_tf32(d[i][jn], al0.z, al1.z, al0.w, al1.w, bl[jn].z, bl[jn].w);
                mma_tf32(d[i][jn], ah0.x, ah1.x, ah0.y, ah1.y, bh[jn].x, bh[jn].y);
                mma_tf32(d[i][jn], ah0.z, ah1.z, ah0.w, ah1.w, bh[jn].z, bh[jn].w);
            }
        }
    };

    auto step = [&](const int bufc, const bool do_load) {
        CP_WAIT1();
        __syncthreads();
        if (do_load) {
            const uint32_t ldoff = (uint32_t)(((bufc + 2) % NSTG) * TILE_BYTES);
            #pragma unroll
            for (int j = 0; j < 4; j++) {
                cp16(a_dst[j] + ldoff,        a_run0 + j * 4, a_sz0);
                cp16(a_dst[j] + ldoff + 8192, a_run1 + j * 4, a_sz1);
                cp16(b_dst[j] + ldoff,        b_run0 + j * 4, b_sz0);
                cp16(b_dst[j] + ldoff + 8192, b_run1 + j * 4, b_sz1);
            }
            a_run0 += BK; a_run1 += BK;
            b_run0 += BK; b_run1 += BK;
        }
        CP_COMMIT();
        compute(bufc);
    };

    // preload stages 0,1
    #pragma unroll
    for (int s = 0; s < 2; s++) {
        const uint32_t o = s * TILE_BYTES;
        #pragma unroll
        for (int j = 0; j < 4; j++) {
            cp16(a_dst[j] + o,        a_src0 + s * BK + j * 4, a_sz0);
            cp16(a_dst[j] + o + 8192, a_src1 + s * BK + j * 4, a_sz1);
            cp16(b_dst[j] + o,        b_src0 + s * BK + j * 4, b_sz0);
            cp16(b_dst[j] + o + 8192, b_src1 + s * BK + j * 4, b_sz1);
        }
        CP_COMMIT();
    }

    #pragma unroll 1
    for (int t = 0; t < 20; t++) {
        step(0, true);
        step(1, true);
        step(2, true);
    }
    step(0, true);
    step(1, true);
    step(2, false);
    step(0, false);
    CP_WAIT0();

    // ---------------- epilogue ----------------
    if (IS_ATT) {
        #pragma unroll
        for (int i = 0; i < 4; i++) {
            float m0 = -CUDART_INF_F, m1 = -CUDART_INF_F;
            #pragma unroll
            for (int jn = 0; jn < 8; jn++) {
                int nb = wn * 64 + jn * 8 + 2 * c;
                float iw0 = invw_s[nb], iw1 = invw_s[nb + 1];
                float bz0 = bias_s[nb], bz1 = bias_s[nb + 1];
                m0 = fmaxf(m0, fmaxf(fmaf(d[i][jn][0], iw0, bz0), fmaf(d[i][jn][1], iw1, bz1)));
                m1 = fmaxf(m1, fmaxf(fmaf(d[i][jn][2], iw0, bz0), fmaf(d[i][jn][3], iw1, bz1)));
            }
            m0 = fmaxf(m0, __shfl_xor_sync(0xffffffffu, m0, 1));
            m0 = fmaxf(m0, __shfl_xor_sync(0xffffffffu, m0, 2));
            m1 = fmaxf(m1, __shfl_xor_sync(0xffffffffu, m1, 1));
            m1 = fmaxf(m1, __shfl_xor_sync(0xffffffffu, m1, 2));
            if (c == 0) {
                redm[(wm * 64 + i * 16 + g) * 2 + wn]     = m0;
                redm[(wm * 64 + i * 16 + g + 8) * 2 + wn] = m1;
            }
        }
        if (fh) {
            float cs[8][2];
            #pragma unroll
            for (int jn = 0; jn < 8; jn++) { cs[jn][0] = 0.0f; cs[jn][1] = 0.0f; }
            #pragma unroll
            for (int i = 0; i < 4; i++) {
                float rf0 = rowfac_s[wm * 64 + i * 16 + g];
                float rf1 = rowfac_s[wm * 64 + i * 16 + g + 8];
                #pragma unroll
                for (int jn = 0; jn < 8; jn++) {
                    cs[jn][0] += d[i][jn][0] * rf0 + d[i][jn][2] * rf1;
                    cs[jn][1] += d[i][jn][1] * rf0 + d[i][jn][3] * rf1;
                }
            }
            #pragma unroll
            for (int jn = 0; jn < 8; jn++) {
                #pragma unroll
                for (int u = 0; u < 2; u++) {
                    float s = cs[jn][u];
                    s += __shfl_xor_sync(0xffffffffu, s, 4);
                    s += __shfl_xor_sync(0xffffffffu, s, 8);
                    s += __shfl_xor_sync(0xffffffffu, s, 16);
                    if (lane < 4) atomicAdd(&csum_s[wn * 64 + jn * 8 + 2 * c + u], s);
                }
            }
        }
        __syncthreads();
        {
            float m = fmaxf(redm[tid * 2 + 0], redm[tid * 2 + 1]);
            int gr = row0 + tid;
            atomicMax(&g_rowmax[gr], enc_f(m * g_invx[gr]));
        }
        if (fh) {
            int n = col0 + tid;
            if (n < NBLK) {
                int b = row0 >> 10;
                atomicAdd(&g_s[b * NBLK + n], csum_s[tid] * invw_s[tid]);
            }
        }
    } else {
        float acc = 0.0f;
        #pragma unroll
        for (int i = 0; i < 4; i++) {
            int m0 = row0 + wm * 64 + i * 16 + g;
            #pragma unroll
            for (int jn = 0; jn < 8; jn++) {
                int n0 = col0 + wn * 64 + jn * 8 + 2 * c;
                float e;
                e = d[i][jn][0] - ((m0 == n0     && m0 < NBLK) ? 1.0f : 0.0f); acc += e * e;
                e = d[i][jn][1] - ((m0 == n0 + 1 && m0 < NBLK) ? 1.0f : 0.0f); acc += e * e;
                e = d[i][jn][2] - ((m0 + 8 == n0     && m0 + 8 < NBLK) ? 1.0f : 0.0f); acc += e * e;
                e = d[i][jn][3] - ((m0 + 8 == n0 + 1 && m0 + 8 < NBLK) ? 1.0f : 0.0f); acc += e * e;
            }
        }
        acc *= dupw;   // 2.0 off-diagonal (symmetric gram), 1.0 diagonal
        #pragma unroll
        for (int o = 16; o; o >>= 1) acc += __shfl_xor_sync(0xffffffffu, acc, o);
        if (lane == 0) csum_s[wid] = acc;
        __syncthreads();
        if (tid == 0) {
            float t = csum_s[0] + csum_s[1] + csum_s[2] + csum_s[3];
            atomicAdd(&g_div, t);
        }
    }
}

template <bool IS_ATT>
__global__ __launch_bounds__(NTH, 2)
void gemm_run(const float* __restrict__ A, const float* __restrict__ B,
              const int* __restrict__ mask) {
    int row0, col0;
    float dupw = 1.0f;
    if (IS_ATT) {
        row0 = blockIdx.y * BM;
        col0 = blockIdx.x * BN;
    } else {
        int bid = blockIdx.x;
        int ti = 0, rem = bid;
        while (rem >= 16 - ti) { rem -= 16 - ti; ti++; }
        int tj = ti + rem;
        row0 = ti * BM;
        col0 = tj * BN;
        dupw = (ti == tj) ? 1.0f : 2.0f;
    }
    gemm_body<IS_ATT>(A, B, mask, row0, col0, dupw);
}

// ---------------- finalize ----------------
template <typename Op>
__device__ __forceinline__ float block_reduce(float v, Op op, float ident, float* sbuf) {
    __syncthreads();
    int tid = threadIdx.x, lane = tid & 31, wid = tid >> 5;
    #pragma unroll
    for (int o = 16; o; o >>= 1) v = op(v, __shfl_down_sync(0xffffffffu, v, o));
    if (lane == 0) sbuf[wid] = v;
    __syncthreads();
    int nw = blockDim.x >> 5;
    if (wid == 0) {
        float w = (lane < nw) ? sbuf[lane] : ident;
        #pragma unroll
        for (int o = 16; o; o >>= 1) w = op(w, __shfl_down_sync(0xffffffffu, w, o));
        if (lane == 0) sbuf[0] = w;
    }
    __syncthreads();
    return sbuf[0];
}
struct OpSum { __device__ float operator()(float a, float b) const { return a + b; } };
struct OpMax { __device__ float operator()(float a, float b) const { return fmaxf(a, b); } };

__global__ void finalize_kernel(const int* __restrict__ mask, float* __restrict__ out) {
    __shared__ float sb_min[32];
    __shared__ float rbuf[32];
    __shared__ float smax[NB_HALF];
    __shared__ float sinvz[NB_HALF];

    int tid = threadIdx.x;
    int lane = tid & 31, wid = tid >> 5;

    {
        int b = wid;
        float mn = CUDART_INF_F;
        for (int t = lane; t < T_PER_B; t += 32) {
            int gr = b * T_PER_B + t;
            if (mask[gr] > 0) mn = fminf(mn, dec_f(g_rowmax[gr]));
        }
        #pragma unroll
        for (int o = 16; o; o >>= 1) mn = fminf(mn, __shfl_down_sync(0xffffffffu, mn, o));
        if (lane == 0) sb_min[b] = mn;
    }
    __syncthreads();

    for (int b = 0; b < NB_HALF; b++) {
        float mx = -CUDART_INF_F;
        for (int n = tid; n < NBLK; n += blockDim.x) mx = fmaxf(mx, g_s[b * NBLK + n]);
        mx = block_reduce(mx, OpMax(), -CUDART_INF_F, rbuf);
        if (tid == 0) smax[b] = mx;
        float se = 0.0f;
        for (int n = tid; n < NBLK; n += blockDim.x) se += expf(g_s[b * NBLK + n] - mx);
        se = block_reduce(se, OpSum(), 0.0f, rbuf);
        if (tid == 0) sinvz[b] = 1.0f / se;
        __syncthreads();
    }

    float usq = 0.0f;
    for (int n = tid; n < NBLK; n += blockDim.x) {
        float tmp = 0.0f;
        #pragma unroll
        for (int b = 0; b < NB_HALF; b++)
            tmp += expf(g_s[b * NBLK + n] - smax[b]) * sinvz[b];
        tmp *= (1.0f / (float)NB_HALF);
        usq += tmp * tmp;
    }
    usq = block_reduce(usq, OpSum(), 0.0f, rbuf);

    if (tid == 0) {
        float mean_min = 0.0f, mean_ab = 0.0f;
        for (int b = 0; b < NB_HALF; b++) { mean_min += sb_min[b]; mean_ab += sb_min[NB_HALF + b]; }
        mean_min *= (1.0f / (float)NB_HALF);
        mean_ab  *= (1.0f / (float)NB_HALF);
        out[0] = 0.2f * sqrtf(g_div);
        out[1] = 2.0f - mean_min + mean_ab;
        out[2] = 0.5f * sqrtf(usq);
    }
}

// ---------------- launch ----------------
extern "C" void kernel_launch(void* const* d_in, const int* in_sizes, int n_in,
                              void* d_out, int out_size) {
    const float* x = nullptr;
    const int*   mask = nullptr;
    const float* w = nullptr;
    for (int i = 0; i < n_in; i++) {
        if (in_sizes[i] == NROWS * DIMK)      x = (const float*)d_in[i];
        else if (in_sizes[i] == NROWS)        mask = (const int*)d_in[i];
        else if (in_sizes[i] == NBLK * DIMK)  w = (const float*)d_in[i];
    }
    float* out = (float*)d_out;

    float* invx_ptr; cudaGetSymbolAddress((void**)&invx_ptr, g_invx);
    float* invw_ptr; cudaGetSymbolAddress((void**)&invw_ptr, g_invw);

    cudaFuncSetAttribute(gemm_run<true>,  cudaFuncAttributeMaxDynamicSharedMemorySize, SMEM_BYTES);
    cudaFuncSetAttribute(gemm_run<false>, cudaFuncAttributeMaxDynamicSharedMemorySize, SMEM_BYTES);

    init_kernel<<<(NROWS + 255) / 256, 256>>>();
    row_invnorm_kernel<<<NROWS, 256>>>(x, invx_ptr);
    row_invnorm_kernel<<<NBLK, 256>>>(w, invw_ptr);
    gemm_run<true><<<dim3(16, 256), NTH, SMEM_BYTES>>>(x, w, mask);
    gemm_run<false><<<dim3(136, 1), NTH, SMEM_BYTES>>>(w, w, nullptr);  // upper triangle
    finalize_kernel<<<1, 1024>>>(mask, out);
}

// round 8
// speedup vs baseline: 7.8764x; 2.1995x over previous
#include <cuda_runtime.h>
#include <cuda_fp16.h>
#include <math_constants.h>
#include <cstdint>

#define DIMK   2048
#define NBLK   2000
#define NPAD   2048
#define NROWS  32768
#define T_PER_B 1024
#define NB_HALF 16

#define BM 128
#define BN 128
#define BKH 64               // k-halfs per stage (128B rows)
#define NITER (DIMK / BKH)   // 32
#define NSTG 3
#define NTH 128              // 4 warps, 64x64 warp tiles

#define TILE_B 16384                     // 128 rows x 128B
#define B_REG_OFF (NSTG * TILE_B)        // 49152
#define EPIL_OFF_B (2 * NSTG * TILE_B)   // 98304
#define SMEM_BYTES (EPIL_OFF_B + 2560)   // 100864 -> 2 CTAs/SM

// ---------------- device scratch ----------------
__device__ __half       g_xh[(size_t)NROWS * DIMK];   // normalized X, fp16
__device__ __half       g_whn[(size_t)NPAD * DIMK];   // normalized W, fp16, zero-padded
__device__ __half       g_whr[(size_t)NPAD * DIMK];   // raw W, fp16, zero-padded
__device__ unsigned int g_rowmax[NROWS];
__device__ float        g_s[NB_HALF * NBLK];
__device__ float        g_div;

// ---------------- helpers ----------------
__device__ __forceinline__ unsigned int enc_f(float f) {
    unsigned int u = __float_as_uint(f);
    return (u & 0x80000000u) ? ~u : (u | 0x80000000u);
}
__device__ __forceinline__ float dec_f(unsigned int u) {
    unsigned int b = (u & 0x80000000u) ? (u ^ 0x80000000u) : ~u;
    return __uint_as_float(b);
}
__device__ __forceinline__ uint32_t smem_u32(const void* p) {
    uint32_t a;
    asm("{ .reg .u64 t; cvta.to.shared.u64 t, %1; cvt.u32.u64 %0, t; }" : "=r"(a) : "l"(p));
    return a;
}
__device__ __forceinline__ void cp16(uint32_t dst, const void* src) {
    asm volatile("cp.async.cg.shared.global [%0], [%1], 16;"
                 :: "r"(dst), "l"(src) : "memory");
}
#define CP_COMMIT() asm volatile("cp.async.commit_group;" ::: "memory")
#define CP_WAIT1()  asm volatile("cp.async.wait_group 1;" ::: "memory")
#define CP_WAIT0()  asm volatile("cp.async.wait_group 0;" ::: "memory")

__device__ __forceinline__ void ldsm_x4(uint32_t* r, uint32_t addr) {
    asm volatile("ldmatrix.sync.aligned.m8n8.x4.shared.b16 {%0,%1,%2,%3}, [%4];"
                 : "=r"(r[0]), "=r"(r[1]), "=r"(r[2]), "=r"(r[3]) : "r"(addr));
}
__device__ __forceinline__ void mma_f16(float* d, uint32_t a0, uint32_t a1,
                                        uint32_t a2, uint32_t a3,
                                        uint32_t b0, uint32_t b1) {
    asm volatile(
        "mma.sync.aligned.m16n8k16.row.col.f32.f16.f16.f32 "
        "{%0,%1,%2,%3}, {%4,%5,%6,%7}, {%8,%9}, {%0,%1,%2,%3};"
        : "+f"(d[0]), "+f"(d[1]), "+f"(d[2]), "+f"(d[3])
        : "r"(a0), "r"(a1), "r"(a2), "r"(a3), "r"(b0), "r"(b1));
}

// ---------------- init ----------------
__global__ void init_kernel() {
    int i = blockIdx.x * blockDim.x + threadIdx.x;
    if (i < NB_HALF * NBLK) g_s[i] = 0.0f;
    if (i < NROWS)          g_rowmax[i] = 0u;
    if (i == 0)             g_div = 0.0f;
}

// ---------------- block-wide sum of 256 lanes ----------------
__device__ __forceinline__ float blk_sum256(float v, float* sm) {
    int lane = threadIdx.x & 31, wid = threadIdx.x >> 5;
    #pragma unroll
    for (int o = 16; o; o >>= 1) v += __shfl_down_sync(0xffffffffu, v, o);
    if (lane == 0) sm[wid] = v;
    __syncthreads();
    float t = (threadIdx.x < 8) ? sm[threadIdx.x] : 0.0f;
    if (wid == 0) {
        #pragma unroll
        for (int o = 4; o; o >>= 1) t += __shfl_down_sync(0xffu, t, o);
        if (lane == 0) sm[0] = t;
    }
    __syncthreads();
    return sm[0];
}

// ---------------- normalize + convert X ----------------
__global__ void conv_x_kernel(const float* __restrict__ X) {
    __shared__ float sm[8];
    int r = blockIdx.x, tid = threadIdx.x;   // 256 threads
    const float4* xp = (const float4*)(X + (size_t)r * DIMK);
    float4 v0 = xp[tid], v1 = xp[tid + 256];
    float ss = v0.x*v0.x + v0.y*v0.y + v0.z*v0.z + v0.w*v0.w
             + v1.x*v1.x + v1.y*v1.y + v1.z*v1.z + v1.w*v1.w;
    ss = blk_sum256(ss, sm);
    float inv = 1.0f / fmaxf(sqrtf(ss), 1e-12f);
    __half2* out = (__half2*)(g_xh + (size_t)r * DIMK);
    out[2*tid + 0]   = __floats2half2_rn(v0.x * inv, v0.y * inv);
    out[2*tid + 1]   = __floats2half2_rn(v0.z * inv, v0.w * inv);
    out[2*(tid+256)] = __floats2half2_rn(v1.x * inv, v1.y * inv);
    out[2*(tid+256)+1] = __floats2half2_rn(v1.z * inv, v1.w * inv);
}

// ---------------- normalize + convert W (padded) ----------------
__global__ void conv_w_kernel(const float* __restrict__ W) {
    __shared__ float sm[8];
    int r = blockIdx.x, tid = threadIdx.x;   // 2048 blocks, 256 threads
    __half2* on = (__half2*)(g_whn + (size_t)r * DIMK);
    __half2* orr = (__half2*)(g_whr + (size_t)r * DIMK);
    if (r < NBLK) {
        const float4* wp = (const float4*)(W + (size_t)r * DIMK);
        float4 v0 = wp[tid], v1 = wp[tid + 256];
        float ss = v0.x*v0.x + v0.y*v0.y + v0.z*v0.z + v0.w*v0.w
                 + v1.x*v1.x + v1.y*v1.y + v1.z*v1.z + v1.w*v1.w;
        ss = blk_sum256(ss, sm);
        float inv = 1.0f / fmaxf(sqrtf(ss), 1e-12f);
        on[2*tid]        = __floats2half2_rn(v0.x*inv, v0.y*inv);
        on[2*tid+1]      = __floats2half2_rn(v0.z*inv, v0.w*inv);
        on[2*(tid+256)]  = __floats2half2_rn(v1.x*inv, v1.y*inv);
        on[2*(tid+256)+1]= __floats2half2_rn(v1.z*inv, v1.w*inv);
        orr[2*tid]        = __floats2half2_rn(v0.x, v0.y);
        orr[2*tid+1]      = __floats2half2_rn(v0.z, v0.w);
        orr[2*(tid+256)]  = __floats2half2_rn(v1.x, v1.y);
        orr[2*(tid+256)+1]= __floats2half2_rn(v1.z, v1.w);
    } else {
        __half2 z = __floats2half2_rn(0.0f, 0.0f);
        on[2*tid] = z; on[2*tid+1] = z; on[2*(tid+256)] = z; on[2*(tid+256)+1] = z;
        orr[2*tid] = z; orr[2*tid+1] = z; orr[2*(tid+256)] = z; orr[2*(tid+256)+1] = z;
    }
}

// ---------------- fp16 mma GEMM: 4 warps, 64x64 warp tiles, ldmatrix ----------------
// smem tile: 128 rows x 128B (64 halfs). Granule swizzle: phys_q = q ^ (row & 7).
template <bool IS_ATT>
__device__ void gemm_body(const __half* __restrict__ A, const __half* __restrict__ B,
                          const int* __restrict__ mask, int row0, int col0, float dupw) {
    extern __shared__ char smc[];
    float* rowfac_s = (float*)(smc + EPIL_OFF_B);  // [128] mask (att)
    float* bias_s   = rowfac_s + 128;              // [128]
    float* csum_s   = bias_s + 128;                // [128]
    float* redm     = csum_s + 128;                // [128][2]

    const int tid  = threadIdx.x;
    const int lane = tid & 31, wid = tid >> 5;
    const int wm = wid >> 1, wn = wid & 1;
    const int g = lane >> 2, c = lane & 3;
    const bool fh = IS_ATT && (row0 < NROWS / 2);

    if (IS_ATT) {
        rowfac_s[tid] = (float)mask[row0 + tid];
        bias_s[tid] = (col0 + tid < NBLK) ? 0.0f : -CUDART_INF_F;
        csum_s[tid] = 0.0f;
    }

    // ---- cp.async setup ----
    const int r_ld = tid >> 1;          // 0..63
    const int h    = tid & 1;
    const int fx   = r_ld & 7;
    const uint32_t sbase = smem_u32(smc);
    uint32_t a_dst[4], b_dst[4];
    #pragma unroll
    for (int j = 0; j < 4; j++) {
        int q = h * 4 + j;
        uint32_t off = (uint32_t)r_ld * 128u + (uint32_t)((q ^ fx) << 4);
        a_dst[j] = sbase + off;
        b_dst[j] = sbase + B_REG_OFF + off;
    }
    const __half* a_run0 = A + (size_t)(row0 + r_ld) * DIMK + h * 32;
    const __half* a_run1 = a_run0 + (size_t)64 * DIMK;
    const __half* b_run0 = B + (size_t)(col0 + r_ld) * DIMK + h * 32;
    const __half* b_run1 = b_run0 + (size_t)64 * DIMK;

    // ---- fragment address precompute ----
    const int mA = lane >> 3, r7 = lane & 7;
    const uint32_t rowA = (uint32_t)((r7 + ((mA & 1) << 3)) * 128);
    const uint32_t rowB = (uint32_t)((r7 + ((mA >> 1) << 3)) * 128);
    const int gbA = mA >> 1, gbB = mA & 1;
    uint32_t xA[4], xB[4];
    #pragma unroll
    for (int ch = 0; ch < 4; ch++) {
        xA[ch] = (uint32_t)(((2 * ch + gbA) ^ r7) << 4);
        xB[ch] = (uint32_t)(((2 * ch + gbB) ^ r7) << 4);
    }
    const uint32_t aFB = sbase + wm * 8192 + rowA;
    const uint32_t bFB = sbase + B_REG_OFF + wn * 8192 + rowB;

    // ---- accumulators ----
    float d[4][8][4];
    #pragma unroll
    for (int i = 0; i < 4; i++)
        #pragma unroll
        for (int j = 0; j < 8; j++)
            #pragma unroll
            for (int r = 0; r < 4; r++) d[i][j][r] = 0.0f;

    auto load_stage = [&](uint32_t bufoff) {
        #pragma unroll
        for (int j = 0; j < 4; j++) {
            cp16(a_dst[j] + bufoff,        a_run0 + j * 8);
            cp16(a_dst[j] + bufoff + 8192, a_run1 + j * 8);
            cp16(b_dst[j] + bufoff,        b_run0 + j * 8);
            cp16(b_dst[j] + bufoff + 8192, b_run1 + j * 8);
        }
        a_run0 += BKH; a_run1 += BKH; b_run0 += BKH; b_run1 += BKH;
    };

    auto compute = [&](const int bufc) {
        const uint32_t ab = aFB + bufc * TILE_B;
        const uint32_t bb = bFB + bufc * TILE_B;
        #pragma unroll
        for (int ch = 0; ch < 4; ch++) {
            uint32_t bf[4][4];
            #pragma unroll
            for (int jp = 0; jp < 4; jp++)
                ldsm_x4(bf[jp], bb + jp * 2048 + xB[ch]);
            #pragma unroll
            for (int ib = 0; ib < 4; ib++) {
                uint32_t af[4];
                ldsm_x4(af, ab + ib * 2048 + xA[ch]);
                #pragma unroll
                for (int jp = 0; jp < 4; jp++) {
                    mma_f16(d[ib][2*jp],   af[0], af[1], af[2], af[3], bf[jp][0], bf[jp][1]);
                    mma_f16(d[ib][2*jp+1], af[0], af[1], af[2], af[3], bf[jp][2], bf[jp][3]);
                }
            }
        }
    };

    auto step = [&](const int bufc, const bool do_load) {
        CP_WAIT1();
        __syncthreads();
        if (do_load) load_stage((uint32_t)(((bufc + 2) % NSTG) * TILE_B));
        CP_COMMIT();
        compute(bufc);
    };

    // preload 0,1
    load_stage(0); CP_COMMIT();
    load_stage(TILE_B); CP_COMMIT();

    #pragma unroll 1
    for (int t = 0; t < 10; t++) {   // s = 0..29
        step(0, true);
        step(1, true);
        step(2, true);
    }
    step(0, false);   // s=30
    step(1, false);   // s=31
    CP_WAIT0();

    // ---------------- epilogue ----------------
    if (IS_ATT) {
        #pragma unroll
        for (int i = 0; i < 4; i++) {
            float m0 = -CUDART_INF_F, m1 = -CUDART_INF_F;
            #pragma unroll
            for (int jn = 0; jn < 8; jn++) {
                int nb = wn * 64 + jn * 8 + 2 * c;
                float bz0 = bias_s[nb], bz1 = bias_s[nb + 1];
                m0 = fmaxf(m0, fmaxf(d[i][jn][0] + bz0, d[i][jn][1] + bz1));
                m1 = fmaxf(m1, fmaxf(d[i][jn][2] + bz0, d[i][jn][3] + bz1));
            }
            m0 = fmaxf(m0, __shfl_xor_sync(0xffffffffu, m0, 1));
            m0 = fmaxf(m0, __shfl_xor_sync(0xffffffffu, m0, 2));
            m1 = fmaxf(m1, __shfl_xor_sync(0xffffffffu, m1, 1));
            m1 = fmaxf(m1, __shfl_xor_sync(0xffffffffu, m1, 2));
            if (c == 0) {
                redm[(wm * 64 + i * 16 + g) * 2 + wn]     = m0;
                redm[(wm * 64 + i * 16 + g + 8) * 2 + wn] = m1;
            }
        }
        if (fh) {
            float cs[8][2];
            #pragma unroll
            for (int jn = 0; jn < 8; jn++) { cs[jn][0] = 0.0f; cs[jn][1] = 0.0f; }
            #pragma unroll
            for (int i = 0; i < 4; i++) {
                float rf0 = rowfac_s[wm * 64 + i * 16 + g];
                float rf1 = rowfac_s[wm * 64 + i * 16 + g + 8];
                #pragma unroll
                for (int jn = 0; jn < 8; jn++) {
                    cs[jn][0] += d[i][jn][0] * rf0 + d[i][jn][2] * rf1;
                    cs[jn][1] += d[i][jn][1] * rf0 + d[i][jn][3] * rf1;
                }
            }
            #pragma unroll
            for (int jn = 0; jn < 8; jn++) {
                #pragma unroll
                for (int u = 0; u < 2; u++) {
                    float s = cs[jn][u];
                    s += __shfl_xor_sync(0xffffffffu, s, 4);
                    s += __shfl_xor_sync(0xffffffffu, s, 8);
                    s += __shfl_xor_sync(0xffffffffu, s, 16);
                    if (lane < 4) atomicAdd(&csum_s[wn * 64 + jn * 8 + 2 * c + u], s);
                }
            }
        }
        __syncthreads();
        {
            float m = fmaxf(redm[tid * 2 + 0], redm[tid * 2 + 1]);
            atomicMax(&g_rowmax[row0 + tid], enc_f(m));
        }
        if (fh) {
            int n = col0 + tid;
            if (n < NBLK) {
                int b = row0 >> 10;
                atomicAdd(&g_s[b * NBLK + n], csum_s[tid]);
            }
        }
    } else {
        float acc = 0.0f;
        #pragma unroll
        for (int i = 0; i < 4; i++) {
            int m0 = row0 + wm * 64 + i * 16 + g;
            #pragma unroll
            for (int jn = 0; jn < 8; jn++) {
                int n0 = col0 + wn * 64 + jn * 8 + 2 * c;
                float e;
                e = d[i][jn][0] - ((m0 == n0     && m0 < NBLK) ? 1.0f : 0.0f); acc += e * e;
                e = d[i][jn][1] - ((m0 == n0 + 1 && m0 < NBLK) ? 1.0f : 0.0f); acc += e * e;
                e = d[i][jn][2] - ((m0 + 8 == n0     && m0 + 8 < NBLK) ? 1.0f : 0.0f); acc += e * e;
                e = d[i][jn][3] - ((m0 + 8 == n0 + 1 && m0 + 8 < NBLK) ? 1.0f : 0.0f); acc += e * e;
            }
        }
        acc *= dupw;
        #pragma unroll
        for (int o = 16; o; o >>= 1) acc += __shfl_xor_sync(0xffffffffu, acc, o);
        if (lane == 0) csum_s[wid] = acc;
        __syncthreads();
        if (tid == 0)
            atomicAdd(&g_div, csum_s[0] + csum_s[1] + csum_s[2] + csum_s[3]);
    }
}

template <bool IS_ATT>
__global__ __launch_bounds__(NTH, 2)
void gemm_run(const __half* __restrict__ A, const __half* __restrict__ B,
              const int* __restrict__ mask) {
    int row0, col0;
    float dupw = 1.0f;
    if (IS_ATT) {
        row0 = blockIdx.y * BM;
        col0 = blockIdx.x * BN;
    } else {
        int bid = blockIdx.x;
        int ti = 0, rem = bid;
        while (rem >= 16 - ti) { rem -= 16 - ti; ti++; }
        int tj = ti + rem;
        row0 = ti * BM;
        col0 = tj * BN;
        dupw = (ti == tj) ? 1.0f : 2.0f;
    }
    gemm_body<IS_ATT>(A, B, mask, row0, col0, dupw);
}

// ---------------- finalize ----------------
template <typename Op>
__device__ __forceinline__ float block_reduce(float v, Op op, float ident, float* sbuf) {
    __syncthreads();
    int tid = threadIdx.x, lane = tid & 31, wid = tid >> 5;
    #pragma unroll
    for (int o = 16; o; o >>= 1) v = op(v, __shfl_down_sync(0xffffffffu, v, o));
    if (lane == 0) sbuf[wid] = v;
    __syncthreads();
    int nw = blockDim.x >> 5;
    if (wid == 0) {
        float w = (lane < nw) ? sbuf[lane] : ident;
        #pragma unroll
        for (int o = 16; o; o >>= 1) w = op(w, __shfl_down_sync(0xffffffffu, w, o));
        if (lane == 0) sbuf[0] = w;
    }
    __syncthreads();
    return sbuf[0];
}
struct OpSum { __device__ float operator()(float a, float b) const { return a + b; } };
struct OpMax { __device__ float operator()(float a, float b) const { return fmaxf(a, b); } };

__global__ void finalize_kernel(const int* __restrict__ mask, float* __restrict__ out) {
    __shared__ float sb_min[32];
    __shared__ float rbuf[32];
    __shared__ float smax[NB_HALF];
    __shared__ float sinvz[NB_HALF];

    int tid = threadIdx.x;
    int lane = tid & 31, wid = tid >> 5;

    {
        int b = wid;
        float mn = CUDART_INF_F;
        for (int t = lane; t < T_PER_B; t += 32) {
            int gr = b * T_PER_B + t;
            if (mask[gr] > 0) mn = fminf(mn, dec_f(g_rowmax[gr]));
        }
        #pragma unroll
        for (int o = 16; o; o >>= 1) mn = fminf(mn, __shfl_down_sync(0xffffffffu, mn, o));
        if (lane == 0) sb_min[b] = mn;
    }
    __syncthreads();

    for (int b = 0; b < NB_HALF; b++) {
        float mx = -CUDART_INF_F;
        for (int n = tid; n < NBLK; n += blockDim.x) mx = fmaxf(mx, g_s[b * NBLK + n]);
        mx = block_reduce(mx, OpMax(), -CUDART_INF_F, rbuf);
        if (tid == 0) smax[b] = mx;
        float se = 0.0f;
        for (int n = tid; n < NBLK; n += blockDim.x) se += expf(g_s[b * NBLK + n] - mx);
        se = block_reduce(se, OpSum(), 0.0f, rbuf);
        if (tid == 0) sinvz[b] = 1.0f / se;
        __syncthreads();
    }

    float usq = 0.0f;
    for (int n = tid; n < NBLK; n += blockDim.x) {
        float tmp = 0.0f;
        #pragma unroll
        for (int b = 0; b < NB_HALF; b++)
            tmp += expf(g_s[b * NBLK + n] - smax[b]) * sinvz[b];
        tmp *= (1.0f / (float)NB_HALF);
        usq += tmp * tmp;
    }
    usq = block_reduce(usq, OpSum(), 0.0f, rbuf);

    if (tid == 0) {
        float mean_min = 0.0f, mean_ab = 0.0f;
        for (int b = 0; b < NB_HALF; b++) { mean_min += sb_min[b]; mean_ab += sb_min[NB_HALF + b]; }
        mean_min *= (1.0f / (float)NB_HALF);
        mean_ab  *= (1.0f / (float)NB_HALF);
        out[0] = 0.2f * sqrtf(g_div);
        out[1] = 2.0f - mean_min + mean_ab;
        out[2] = 0.5f * sqrtf(usq);
    }
}

// ---------------- launch ----------------
extern "C" void kernel_launch(void* const* d_in, const int* in_sizes, int n_in,
                              void* d_out, int out_size) {
    const float* x = nullptr;
    const int*   mask = nullptr;
    const float* w = nullptr;
    for (int i = 0; i < n_in; i++) {
        if (in_sizes[i] == NROWS * DIMK)      x = (const float*)d_in[i];
        else if (in_sizes[i] == NROWS)        mask = (const int*)d_in[i];
        else if (in_sizes[i] == NBLK * DIMK)  w = (const float*)d_in[i];
    }
    float* out = (float*)d_out;

    __half* xh_ptr;  cudaGetSymbolAddress((void**)&xh_ptr,  g_xh);
    __half* whn_ptr; cudaGetSymbolAddress((void**)&whn_ptr, g_whn);
    __half* whr_ptr; cudaGetSymbolAddress((void**)&whr_ptr, g_whr);

    cudaFuncSetAttribute(gemm_run<true>,  cudaFuncAttributeMaxDynamicSharedMemorySize, SMEM_BYTES);
    cudaFuncSetAttribute(gemm_run<false>, cudaFuncAttributeMaxDynamicSharedMemorySize, SMEM_BYTES);

    init_kernel<<<(NROWS + 255) / 256, 256>>>();
    conv_x_kernel<<<NROWS, 256>>>(x);
    conv_w_kernel<<<NPAD, 256>>>(w);
    gemm_run<true><<<dim3(16, 256), NTH, SMEM_BYTES>>>(xh_ptr, whn_ptr, mask);
    gemm_run<false><<<dim3(136, 1), NTH, SMEM_BYTES>>>(whr_ptr, whr_ptr, nullptr);
    finalize_kernel<<<1, 1024>>>(mask, out);
}

// round 9
// speedup vs baseline: 7.9988x; 1.0155x over previous
#include <cuda_runtime.h>
#include <cuda_fp16.h>
#include <math_constants.h>
#include <cstdint>

#define DIMK   2048
#define NBLK   2000
#define NPAD   2048
#define NROWS  32768
#define T_PER_B 1024
#define NB_HALF 16

#define BM 128
#define BN 128
#define BKH 32               // k-halfs per stage (64B data / 80B stride rows)
#define NITER (DIMK / BKH)   // 64
#define NSTG 3
#define NTH 128              // 4 warps, 64x64 warp tiles

#define ROW_STRIDE 80                    // padded row stride (conflict-free, no swizzle)
#define TILE_B (128 * ROW_STRIDE)        // 10240 B per tile
#define B_REG_OFF (NSTG * TILE_B)        // 30720
#define EPIL_OFF_B (2 * NSTG * TILE_B)   // 61440
#define SMEM_BYTES (EPIL_OFF_B + 2560)   // 64000 -> 3 CTAs/SM

#define N_ATT_CTAS 4096
#define N_DIV_CTAS 136

// ---------------- device scratch ----------------
__device__ __half       g_xh[(size_t)NROWS * DIMK];
__device__ __half       g_whn[(size_t)NPAD * DIMK];
__device__ __half       g_whr[(size_t)NPAD * DIMK];
__device__ unsigned int g_rowmax[NROWS];
__device__ float        g_s[NB_HALF * NBLK];
__device__ float        g_div;

// ---------------- helpers ----------------
__device__ __forceinline__ unsigned int enc_f(float f) {
    unsigned int u = __float_as_uint(f);
    return (u & 0x80000000u) ? ~u : (u | 0x80000000u);
}
__device__ __forceinline__ float dec_f(unsigned int u) {
    unsigned int b = (u & 0x80000000u) ? (u ^ 0x80000000u) : ~u;
    return __uint_as_float(b);
}
__device__ __forceinline__ uint32_t smem_u32(const void* p) {
    uint32_t a;
    asm("{ .reg .u64 t; cvta.to.shared.u64 t, %1; cvt.u32.u64 %0, t; }" : "=r"(a) : "l"(p));
    return a;
}
__device__ __forceinline__ void cp16(uint32_t dst, const void* src) {
    asm volatile("cp.async.cg.shared.global [%0], [%1], 16;"
                 :: "r"(dst), "l"(src) : "memory");
}
#define CP_COMMIT() asm volatile("cp.async.commit_group;" ::: "memory")
#define CP_WAIT1()  asm volatile("cp.async.wait_group 1;" ::: "memory")
#define CP_WAIT0()  asm volatile("cp.async.wait_group 0;" ::: "memory")

__device__ __forceinline__ void ldsm_x4(uint32_t* r, uint32_t addr) {
    asm volatile("ldmatrix.sync.aligned.m8n8.x4.shared.b16 {%0,%1,%2,%3}, [%4];"
                 : "=r"(r[0]), "=r"(r[1]), "=r"(r[2]), "=r"(r[3]) : "r"(addr));
}
__device__ __forceinline__ void mma_f16(float* d, uint32_t a0, uint32_t a1,
                                        uint32_t a2, uint32_t a3,
                                        uint32_t b0, uint32_t b1) {
    asm volatile(
        "mma.sync.aligned.m16n8k16.row.col.f32.f16.f16.f32 "
        "{%0,%1,%2,%3}, {%4,%5,%6,%7}, {%8,%9}, {%0,%1,%2,%3};"
        : "+f"(d[0]), "+f"(d[1]), "+f"(d[2]), "+f"(d[3])
        : "r"(a0), "r"(a1), "r"(a2), "r"(a3), "r"(b0), "r"(b1));
}

// ---------------- init ----------------
__global__ void init_kernel() {
    int i = blockIdx.x * blockDim.x + threadIdx.x;
    if (i < NB_HALF * NBLK) g_s[i] = 0.0f;
    if (i < NROWS)          g_rowmax[i] = 0u;
    if (i == 0)             g_div = 0.0f;
}

__device__ __forceinline__ float blk_sum256(float v, float* sm) {
    int lane = threadIdx.x & 31, wid = threadIdx.x >> 5;
    #pragma unroll
    for (int o = 16; o; o >>= 1) v += __shfl_down_sync(0xffffffffu, v, o);
    if (lane == 0) sm[wid] = v;
    __syncthreads();
    float t = (threadIdx.x < 8) ? sm[threadIdx.x] : 0.0f;
    if (wid == 0) {
        #pragma unroll
        for (int o = 4; o; o >>= 1) t += __shfl_down_sync(0xffu, t, o);
        if (lane == 0) sm[0] = t;
    }
    __syncthreads();
    return sm[0];
}

// ---------------- normalize + convert X ----------------
__global__ void conv_x_kernel(const float* __restrict__ X) {
    __shared__ float sm[8];
    int r = blockIdx.x, tid = threadIdx.x;
    const float4* xp = (const float4*)(X + (size_t)r * DIMK);
    float4 v0 = xp[tid], v1 = xp[tid + 256];
    float ss = v0.x*v0.x + v0.y*v0.y + v0.z*v0.z + v0.w*v0.w
             + v1.x*v1.x + v1.y*v1.y + v1.z*v1.z + v1.w*v1.w;
    ss = blk_sum256(ss, sm);
    float inv = 1.0f / fmaxf(sqrtf(ss), 1e-12f);
    __half2* out = (__half2*)(g_xh + (size_t)r * DIMK);
    out[2*tid + 0]     = __floats2half2_rn(v0.x * inv, v0.y * inv);
    out[2*tid + 1]     = __floats2half2_rn(v0.z * inv, v0.w * inv);
    out[2*(tid+256)]   = __floats2half2_rn(v1.x * inv, v1.y * inv);
    out[2*(tid+256)+1] = __floats2half2_rn(v1.z * inv, v1.w * inv);
}

// ---------------- normalize + convert W (padded) ----------------
__global__ void conv_w_kernel(const float* __restrict__ W) {
    __shared__ float sm[8];
    int r = blockIdx.x, tid = threadIdx.x;
    __half2* on  = (__half2*)(g_whn + (size_t)r * DIMK);
    __half2* orr = (__half2*)(g_whr + (size_t)r * DIMK);
    if (r < NBLK) {
        const float4* wp = (const float4*)(W + (size_t)r * DIMK);
        float4 v0 = wp[tid], v1 = wp[tid + 256];
        float ss = v0.x*v0.x + v0.y*v0.y + v0.z*v0.z + v0.w*v0.w
                 + v1.x*v1.x + v1.y*v1.y + v1.z*v1.z + v1.w*v1.w;
        ss = blk_sum256(ss, sm);
        float inv = 1.0f / fmaxf(sqrtf(ss), 1e-12f);
        on[2*tid]         = __floats2half2_rn(v0.x*inv, v0.y*inv);
        on[2*tid+1]       = __floats2half2_rn(v0.z*inv, v0.w*inv);
        on[2*(tid+256)]   = __floats2half2_rn(v1.x*inv, v1.y*inv);
        on[2*(tid+256)+1] = __floats2half2_rn(v1.z*inv, v1.w*inv);
        orr[2*tid]         = __floats2half2_rn(v0.x, v0.y);
        orr[2*tid+1]       = __floats2half2_rn(v0.z, v0.w);
        orr[2*(tid+256)]   = __floats2half2_rn(v1.x, v1.y);
        orr[2*(tid+256)+1] = __floats2half2_rn(v1.z, v1.w);
    } else {
        __half2 z = __floats2half2_rn(0.0f, 0.0f);
        on[2*tid] = z; on[2*tid+1] = z; on[2*(tid+256)] = z; on[2*(tid+256)+1] = z;
        orr[2*tid] = z; orr[2*tid+1] = z; orr[2*(tid+256)] = z; orr[2*(tid+256)+1] = z;
    }
}

// ---------------- fp16 mma GEMM: 3 CTAs/SM, merged att+div grid ----------------
// smem tile: 128 rows x 64B data at 80B stride (conflict-free, unswizzled).
__global__ __launch_bounds__(NTH, 3)
void gemm_run(const int* __restrict__ mask) {
    extern __shared__ char smc[];
    float* rowfac_s = (float*)(smc + EPIL_OFF_B);  // [128]
    float* bias_s   = rowfac_s + 128;              // [128]
    float* csum_s   = bias_s + 128;                // [128]
    float* redm     = csum_s + 128;                // [128][2]

    const int tid  = threadIdx.x;
    const int lane = tid & 31, wid = tid >> 5;
    const int wm = wid >> 1, wn = wid & 1;
    const int g = lane >> 2, c = lane & 3;

    // ---- decode tile ----
    const int bid = blockIdx.x;
    const bool is_att = (bid < N_ATT_CTAS);
    int row0, col0;
    float dupw = 1.0f;
    const __half *A, *B;
    if (is_att) {
        col0 = (bid & 15) * BN;
        row0 = (bid >> 4) * BM;
        A = g_xh; B = g_whn;
    } else {
        int b = bid - N_ATT_CTAS;
        int ti = 0, rem = b;
        while (rem >= 16 - ti) { rem -= 16 - ti; ti++; }
        int tj = ti + rem;
        row0 = ti * BM;
        col0 = tj * BN;
        dupw = (ti == tj) ? 1.0f : 2.0f;
        A = g_whr; B = g_whr;
    }
    const bool fh = is_att && (row0 < NROWS / 2);

    if (is_att) {
        rowfac_s[tid] = (float)mask[row0 + tid];
        bias_s[tid] = (col0 + tid < NBLK) ? 0.0f : -CUDART_INF_F;
        csum_s[tid] = 0.0f;
    }

    // ---- cp.async setup: idx = tid + i*128 -> q = tid&3, r = (tid>>2) + 32*i ----
    const int q  = tid & 3;
    const int r0 = tid >> 2;
    const uint32_t sbase = smem_u32(smc);
    const uint32_t a_dst0 = sbase + (uint32_t)(r0 * ROW_STRIDE + q * 16);
    const uint32_t b_dst0 = a_dst0 + B_REG_OFF;
    const __half* a_run = A + (size_t)(row0 + r0) * DIMK + q * 8;
    const __half* b_run = B + (size_t)(col0 + r0) * DIMK + q * 8;

    // ---- fragment addresses ----
    const int mA = lane >> 3, r7 = lane & 7;
    const int gbA = mA >> 1, gbB = mA & 1;
    const uint32_t aFB = sbase + (uint32_t)((wm * 64 + r7 + ((mA & 1) << 3)) * ROW_STRIDE);
    const uint32_t bFB = sbase + B_REG_OFF + (uint32_t)((wn * 64 + r7 + ((mA >> 1) << 3)) * ROW_STRIDE);
    const uint32_t xA0 = (uint32_t)(gbA * 16), xA1 = xA0 + 32;
    const uint32_t xB0 = (uint32_t)(gbB * 16), xB1 = xB0 + 32;

    // ---- accumulators ----
    float d[4][8][4];
    #pragma unroll
    for (int i = 0; i < 4; i++)
        #pragma unroll
        for (int j = 0; j < 8; j++)
            #pragma unroll
            for (int r = 0; r < 4; r++) d[i][j][r] = 0.0f;

    auto load_stage = [&](uint32_t bufoff) {
        #pragma unroll
        for (int i = 0; i < 4; i++) {
            cp16(a_dst0 + bufoff + i * (32 * ROW_STRIDE), a_run + (size_t)i * 32 * DIMK);
            cp16(b_dst0 + bufoff + i * (32 * ROW_STRIDE), b_run + (size_t)i * 32 * DIMK);
        }
        a_run += BKH; b_run += BKH;
    };

    auto compute_chunk = [&](uint32_t ab, uint32_t bb, uint32_t xa, uint32_t xb) {
        uint32_t bf[4][4];
        #pragma unroll
        for (int jp = 0; jp < 4; jp++)
            ldsm_x4(bf[jp], bb + jp * (16 * ROW_STRIDE) + xb);
        #pragma unroll
        for (int ib = 0; ib < 4; ib++) {
            uint32_t af[4];
            ldsm_x4(af, ab + ib * (16 * ROW_STRIDE) + xa);
            #pragma unroll
            for (int jp = 0; jp < 4; jp++) {
                mma_f16(d[ib][2*jp],   af[0], af[1], af[2], af[3], bf[jp][0], bf[jp][1]);
                mma_f16(d[ib][2*jp+1], af[0], af[1], af[2], af[3], bf[jp][2], bf[jp][3]);
            }
        }
    };

    // preload stages 0,1
    load_stage(0); CP_COMMIT();
    load_stage(TILE_B); CP_COMMIT();

    int bufc = 0, bufl = 2;
    #pragma unroll 1
    for (int s = 0; s < NITER; s++) {
        CP_WAIT1();
        __syncthreads();
        if (s < NITER - 2) load_stage((uint32_t)(bufl * TILE_B));
        CP_COMMIT();
        const uint32_t ab = aFB + bufc * TILE_B;
        const uint32_t bb = bFB + bufc * TILE_B;
        compute_chunk(ab, bb, xA0, xB0);
        compute_chunk(ab, bb, xA1, xB1);
        bufc = (bufc == 2) ? 0 : bufc + 1;
        bufl = (bufl == 2) ? 0 : bufl + 1;
    }
    CP_WAIT0();

    // ---------------- epilogue ----------------
    if (is_att) {
        #pragma unroll
        for (int i = 0; i < 4; i++) {
            float m0 = -CUDART_INF_F, m1 = -CUDART_INF_F;
            #pragma unroll
            for (int jn = 0; jn < 8; jn++) {
                int nb = wn * 64 + jn * 8 + 2 * c;
                float bz0 = bias_s[nb], bz1 = bias_s[nb + 1];
                m0 = fmaxf(m0, fmaxf(d[i][jn][0] + bz0, d[i][jn][1] + bz1));
                m1 = fmaxf(m1, fmaxf(d[i][jn][2] + bz0, d[i][jn][3] + bz1));
            }
            m0 = fmaxf(m0, __shfl_xor_sync(0xffffffffu, m0, 1));
            m0 = fmaxf(m0, __shfl_xor_sync(0xffffffffu, m0, 2));
            m1 = fmaxf(m1, __shfl_xor_sync(0xffffffffu, m1, 1));
            m1 = fmaxf(m1, __shfl_xor_sync(0xffffffffu, m1, 2));
            if (c == 0) {
                redm[(wm * 64 + i * 16 + g) * 2 + wn]     = m0;
                redm[(wm * 64 + i * 16 + g + 8) * 2 + wn] = m1;
            }
        }
        if (fh) {
            float cs[8][2];
            #pragma unroll
            for (int jn = 0; jn < 8; jn++) { cs[jn][0] = 0.0f; cs[jn][1] = 0.0f; }
            #pragma unroll
            for (int i = 0; i < 4; i++) {
                float rf0 = rowfac_s[wm * 64 + i * 16 + g];
                float rf1 = rowfac_s[wm * 64 + i * 16 + g + 8];
                #pragma unroll
                for (int jn = 0; jn < 8; jn++) {
                    cs[jn][0] += d[i][jn][0] * rf0 + d[i][jn][2] * rf1;
                    cs[jn][1] += d[i][jn][1] * rf0 + d[i][jn][3] * rf1;
                }
            }
            #pragma unroll
            for (int jn = 0; jn < 8; jn++) {
                #pragma unroll
                for (int u = 0; u < 2; u++) {
                    float s = cs[jn][u];
                    s += __shfl_xor_sync(0xffffffffu, s, 4);
                    s += __shfl_xor_sync(0xffffffffu, s, 8);
                    s += __shfl_xor_sync(0xffffffffu, s, 16);
                    if (lane < 4) atomicAdd(&csum_s[wn * 64 + jn * 8 + 2 * c + u], s);
                }
            }
        }
        __syncthreads();
        {
            float m = fmaxf(redm[tid * 2 + 0], redm[tid * 2 + 1]);
            atomicMax(&g_rowmax[row0 + tid], enc_f(m));
        }
        if (fh) {
            int n = col0 + tid;
            if (n < NBLK) {
                int b = row0 >> 10;
                atomicAdd(&g_s[b * NBLK + n], csum_s[tid]);
            }
        }
    } else {
        float acc = 0.0f;
        #pragma unroll
        for (int i = 0; i < 4; i++) {
            int m0 = row0 + wm * 64 + i * 16 + g;
            #pragma unroll
            for (int jn = 0; jn < 8; jn++) {
                int n0 = col0 + wn * 64 + jn * 8 + 2 * c;
                float e;
                e = d[i][jn][0] - ((m0 == n0     && m0 < NBLK) ? 1.0f : 0.0f); acc += e * e;
                e = d[i][jn][1] - ((m0 == n0 + 1 && m0 < NBLK) ? 1.0f : 0.0f); acc += e * e;
                e = d[i][jn][2] - ((m0 + 8 == n0     && m0 + 8 < NBLK) ? 1.0f : 0.0f); acc += e * e;
                e = d[i][jn][3] - ((m0 + 8 == n0 + 1 && m0 + 8 < NBLK) ? 1.0f : 0.0f); acc += e * e;
            }
        }
        acc *= dupw;
        #pragma unroll
        for (int o = 16; o; o >>= 1) acc += __shfl_xor_sync(0xffffffffu, acc, o);
        if (lane == 0) csum_s[wid] = acc;
        __syncthreads();
        if (tid == 0)
            atomicAdd(&g_div, csum_s[0] + csum_s[1] + csum_s[2] + csum_s[3]);
    }
}

// ---------------- finalize ----------------
template <typename Op>
__device__ __forceinline__ float block_reduce(float v, Op op, float ident, float* sbuf) {
    __syncthreads();
    int tid = threadIdx.x, lane = tid & 31, wid = tid >> 5;
    #pragma unroll
    for (int o = 16; o; o >>= 1) v = op(v, __shfl_down_sync(0xffffffffu, v, o));
    if (lane == 0) sbuf[wid] = v;
    __syncthreads();
    int nw = blockDim.x >> 5;
    if (wid == 0) {
        float w = (lane < nw) ? sbuf[lane] : ident;
        #pragma unroll
        for (int o = 16; o; o >>= 1) w = op(w, __shfl_down_sync(0xffffffffu, w, o));
        if (lane == 0) sbuf[0] = w;
    }
    __syncthreads();
    return sbuf[0];
}
struct OpSum { __device__ float operator()(float a, float b) const { return a + b; } };
struct OpMax { __device__ float operator()(float a, float b) const { return fmaxf(a, b); } };

__global__ void finalize_kernel(const int* __restrict__ mask, float* __restrict__ out) {
    __shared__ float sb_min[32];
    __shared__ float rbuf[32];
    __shared__ float smax[NB_HALF];
    __shared__ float sinvz[NB_HALF];

    int tid = threadIdx.x;
    int lane = tid & 31, wid = tid >> 5;

    {
        int b = wid;
        float mn = CUDART_INF_F;
        for (int t = lane; t < T_PER_B; t += 32) {
            int gr = b * T_PER_B + t;
            if (mask[gr] > 0) mn = fminf(mn, dec_f(g_rowmax[gr]));
        }
        #pragma unroll
        for (int o = 16; o; o >>= 1) mn = fminf(mn, __shfl_down_sync(0xffffffffu, mn, o));
        if (lane == 0) sb_min[b] = mn;
    }
    __syncthreads();

    for (int b = 0; b < NB_HALF; b++) {
        float mx = -CUDART_INF_F;
        for (int n = tid; n < NBLK; n += blockDim.x) mx = fmaxf(mx, g_s[b * NBLK + n]);
        mx = block_reduce(mx, OpMax(), -CUDART_INF_F, rbuf);
        if (tid == 0) smax[b] = mx;
        float se = 0.0f;
        for (int n = tid; n < NBLK; n += blockDim.x) se += expf(g_s[b * NBLK + n] - mx);
        se = block_reduce(se, OpSum(), 0.0f, rbuf);
        if (tid == 0) sinvz[b] = 1.0f / se;
        __syncthreads();
    }

    float usq = 0.0f;
    for (int n = tid; n < NBLK; n += blockDim.x) {
        float tmp = 0.0f;
        #pragma unroll
        for (int b = 0; b < NB_HALF; b++)
            tmp += expf(g_s[b * NBLK + n] - smax[b]) * sinvz[b];
        tmp *= (1.0f / (float)NB_HALF);
        usq += tmp * tmp;
    }
    usq = block_reduce(usq, OpSum(), 0.0f, rbuf);

    if (tid == 0) {
        float mean_min = 0.0f, mean_ab = 0.0f;
        for (int b = 0; b < NB_HALF; b++) { mean_min += sb_min[b]; mean_ab += sb_min[NB_HALF + b]; }
        mean_min *= (1.0f / (float)NB_HALF);
        mean_ab  *= (1.0f / (float)NB_HALF);
        out[0] = 0.2f * sqrtf(g_div);
        out[1] = 2.0f - mean_min + mean_ab;
        out[2] = 0.5f * sqrtf(usq);
    }
}

// ---------------- launch ----------------
extern "C" void kernel_launch(void* const* d_in, const int* in_sizes, int n_in,
                              void* d_out, int out_size) {
    const float* x = nullptr;
    const int*   mask = nullptr;
    const float* w = nullptr;
    for (int i = 0; i < n_in; i++) {
        if (in_sizes[i] == NROWS * DIMK)      x = (const float*)d_in[i];
        else if (in_sizes[i] == NROWS)        mask = (const int*)d_in[i];
        else if (in_sizes[i] == NBLK * DIMK)  w = (const float*)d_in[i];
    }
    float* out = (float*)d_out;

    cudaFuncSetAttribute(gemm_run, cudaFuncAttributeMaxDynamicSharedMemorySize, SMEM_BYTES);

    init_kernel<<<(NROWS + 255) / 256, 256>>>();
    conv_x_kernel<<<NROWS, 256>>>(x);
    conv_w_kernel<<<NPAD, 256>>>(w);
    gemm_run<<<N_ATT_CTAS + N_DIV_CTAS, NTH, SMEM_BYTES>>>(mask);
    finalize_kernel<<<1, 1024>>>(mask, out);
}

// round 10
// speedup vs baseline: 8.1326x; 1.0167x over previous
#include <cuda_runtime.h>
#include <cuda_fp16.h>
#include <math_constants.h>
#include <cstdint>

#define DIMK   2048
#define NBLK   2000
#define NPAD   2048
#define NROWS  32768
#define T_PER_B 1024
#define NB_HALF 16

#define BM 128
#define BN 128
#define BKH 32               // k-halfs per stage
#define NITER (DIMK / BKH)   // 64
#define NSTG 3
#define NTH 256              // 8 warps, 64x32 warp tiles

#define ROW_STRIDE 80                    // padded row stride (conflict-free)
#define TILE_B (128 * ROW_STRIDE)        // 10240 B
#define B_REG_OFF (NSTG * TILE_B)        // 30720
#define EPIL_OFF_B (2 * NSTG * TILE_B)   // 61440
#define SMEM_BYTES (EPIL_OFF_B + 3712)   // 65152 -> 2 CTAs/SM

#define N_ATT_CTAS 4096
#define N_DIV_CTAS 136

// ---------------- device scratch ----------------
__device__ __half       g_xh[(size_t)NROWS * DIMK];
__device__ __half       g_whn[(size_t)NPAD * DIMK];
__device__ __half       g_whr[(size_t)NPAD * DIMK];
__device__ unsigned int g_rowmax[NROWS];
__device__ float        g_s[NB_HALF * NBLK];
__device__ float        g_div;

// ---------------- helpers ----------------
__device__ __forceinline__ unsigned int enc_f(float f) {
    unsigned int u = __float_as_uint(f);
    return (u & 0x80000000u) ? ~u : (u | 0x80000000u);
}
__device__ __forceinline__ float dec_f(unsigned int u) {
    unsigned int b = (u & 0x80000000u) ? (u ^ 0x80000000u) : ~u;
    return __uint_as_float(b);
}
__device__ __forceinline__ uint32_t smem_u32(const void* p) {
    uint32_t a;
    asm("{ .reg .u64 t; cvta.to.shared.u64 t, %1; cvt.u32.u64 %0, t; }" : "=r"(a) : "l"(p));
    return a;
}
__device__ __forceinline__ void cp16(uint32_t dst, const void* src) {
    asm volatile("cp.async.cg.shared.global [%0], [%1], 16;"
                 :: "r"(dst), "l"(src) : "memory");
}
#define CP_COMMIT() asm volatile("cp.async.commit_group;" ::: "memory")
#define CP_WAIT1()  asm volatile("cp.async.wait_group 1;" ::: "memory")
#define CP_WAIT0()  asm volatile("cp.async.wait_group 0;" ::: "memory")

__device__ __forceinline__ void ldsm_x4(uint32_t* r, uint32_t addr) {
    asm volatile("ldmatrix.sync.aligned.m8n8.x4.shared.b16 {%0,%1,%2,%3}, [%4];"
                 : "=r"(r[0]), "=r"(r[1]), "=r"(r[2]), "=r"(r[3]) : "r"(addr));
}
__device__ __forceinline__ void mma_f16(float* d, uint32_t a0, uint32_t a1,
                                        uint32_t a2, uint32_t a3,
                                        uint32_t b0, uint32_t b1) {
    asm volatile(
        "mma.sync.aligned.m16n8k16.row.col.f32.f16.f16.f32 "
        "{%0,%1,%2,%3}, {%4,%5,%6,%7}, {%8,%9}, {%0,%1,%2,%3};"
        : "+f"(d[0]), "+f"(d[1]), "+f"(d[2]), "+f"(d[3])
        : "r"(a0), "r"(a1), "r"(a2), "r"(a3), "r"(b0), "r"(b1));
}

// ---------------- init ----------------
__global__ void init_kernel() {
    int i = blockIdx.x * blockDim.x + threadIdx.x;
    if (i < NB_HALF * NBLK) g_s[i] = 0.0f;
    if (i < NROWS)          g_rowmax[i] = 0u;
    if (i == 0)             g_div = 0.0f;
}

__device__ __forceinline__ float blk_sum256(float v, float* sm) {
    int lane = threadIdx.x & 31, wid = threadIdx.x >> 5;
    #pragma unroll
    for (int o = 16; o; o >>= 1) v += __shfl_down_sync(0xffffffffu, v, o);
    if (lane == 0) sm[wid] = v;
    __syncthreads();
    float t = (threadIdx.x < 8) ? sm[threadIdx.x] : 0.0f;
    if (wid == 0) {
        #pragma unroll
        for (int o = 4; o; o >>= 1) t += __shfl_down_sync(0xffu, t, o);
        if (lane == 0) sm[0] = t;
    }
    __syncthreads();
    return sm[0];
}

// ---------------- normalize + convert X ----------------
__global__ void conv_x_kernel(const float* __restrict__ X) {
    __shared__ float sm[8];
    int r = blockIdx.x, tid = threadIdx.x;
    const float4* xp = (const float4*)(X + (size_t)r * DIMK);
    float4 v0 = xp[tid], v1 = xp[tid + 256];
    float ss = v0.x*v0.x + v0.y*v0.y + v0.z*v0.z + v0.w*v0.w
             + v1.x*v1.x + v1.y*v1.y + v1.z*v1.z + v1.w*v1.w;
    ss = blk_sum256(ss, sm);
    float inv = 1.0f / fmaxf(sqrtf(ss), 1e-12f);
    __half2* out = (__half2*)(g_xh + (size_t)r * DIMK);
    out[2*tid + 0]     = __floats2half2_rn(v0.x * inv, v0.y * inv);
    out[2*tid + 1]     = __floats2half2_rn(v0.z * inv, v0.w * inv);
    out[2*(tid+256)]   = __floats2half2_rn(v1.x * inv, v1.y * inv);
    out[2*(tid+256)+1] = __floats2half2_rn(v1.z * inv, v1.w * inv);
}

// ---------------- normalize + convert W (padded) ----------------
__global__ void conv_w_kernel(const float* __restrict__ W) {
    __shared__ float sm[8];
    int r = blockIdx.x, tid = threadIdx.x;
    __half2* on  = (__half2*)(g_whn + (size_t)r * DIMK);
    __half2* orr = (__half2*)(g_whr + (size_t)r * DIMK);
    if (r < NBLK) {
        const float4* wp = (const float4*)(W + (size_t)r * DIMK);
        float4 v0 = wp[tid], v1 = wp[tid + 256];
        float ss = v0.x*v0.x + v0.y*v0.y + v0.z*v0.z + v0.w*v0.w
                 + v1.x*v1.x + v1.y*v1.y + v1.z*v1.z + v1.w*v1.w;
        ss = blk_sum256(ss, sm);
        float inv = 1.0f / fmaxf(sqrtf(ss), 1e-12f);
        on[2*tid]         = __floats2half2_rn(v0.x*inv, v0.y*inv);
        on[2*tid+1]       = __floats2half2_rn(v0.z*inv, v0.w*inv);
        on[2*(tid+256)]   = __floats2half2_rn(v1.x*inv, v1.y*inv);
        on[2*(tid+256)+1] = __floats2half2_rn(v1.z*inv, v1.w*inv);
        orr[2*tid]         = __floats2half2_rn(v0.x, v0.y);
        orr[2*tid+1]       = __floats2half2_rn(v0.z, v0.w);
        orr[2*(tid+256)]   = __floats2half2_rn(v1.x, v1.y);
        orr[2*(tid+256)+1] = __floats2half2_rn(v1.z, v1.w);
    } else {
        __half2 z = __floats2half2_rn(0.0f, 0.0f);
        on[2*tid] = z; on[2*tid+1] = z; on[2*(tid+256)] = z; on[2*(tid+256)+1] = z;
        orr[2*tid] = z; orr[2*tid+1] = z; orr[2*(tid+256)] = z; orr[2*(tid+256)+1] = z;
    }
}

// ---------------- fp16 mma GEMM: 8 warps (2x4), 64x32 warp tiles ----------------
__global__ __launch_bounds__(NTH, 2)
void gemm_run(const int* __restrict__ mask) {
    extern __shared__ char smc[];
    float* rowfac_s = (float*)(smc + EPIL_OFF_B);  // [128]
    float* bias_s   = rowfac_s + 128;              // [128]
    float* csum_s   = bias_s + 128;                // [128]
    float* redm     = csum_s + 128;                // [128][4]

    const int tid  = threadIdx.x;
    const int lane = tid & 31, wid = tid >> 5;
    const int wm = wid >> 2, wn = wid & 3;        // 2 x 4 warp grid
    const int g = lane >> 2, c = lane & 3;

    // ---- decode tile ----
    const int bid = blockIdx.x;
    const bool is_att = (bid < N_ATT_CTAS);
    int row0, col0;
    float dupw = 1.0f;
    const __half *A, *B;
    if (is_att) {
        col0 = (bid & 15) * BN;
        row0 = (bid >> 4) * BM;
        A = g_xh; B = g_whn;
    } else {
        int b = bid - N_ATT_CTAS;
        int ti = 0, rem = b;
        while (rem >= 16 - ti) { rem -= 16 - ti; ti++; }
        int tj = ti + rem;
        row0 = ti * BM;
        col0 = tj * BN;
        dupw = (ti == tj) ? 1.0f : 2.0f;
        A = g_whr; B = g_whr;
    }
    const bool fh = is_att && (row0 < NROWS / 2);

    if (is_att && tid < 128) {
        rowfac_s[tid] = (float)mask[row0 + tid];
        bias_s[tid] = (col0 + tid < NBLK) ? 0.0f : -CUDART_INF_F;
        csum_s[tid] = 0.0f;
    }

    // ---- cp.async setup: 256 threads -> each does 2 rows per tile ----
    const int q  = tid & 3;
    const int r0 = tid >> 2;            // 0..63
    const uint32_t sbase = smem_u32(smc);
    const uint32_t a_dst0 = sbase + (uint32_t)(r0 * ROW_STRIDE + q * 16);
    const uint32_t b_dst0 = a_dst0 + B_REG_OFF;
    const __half* a_run = A + (size_t)(row0 + r0) * DIMK + q * 8;
    const __half* b_run = B + (size_t)(col0 + r0) * DIMK + q * 8;

    // ---- fragment addresses ----
    const int mA = lane >> 3, r7 = lane & 7;
    const int gbA = mA >> 1, gbB = mA & 1;
    const uint32_t aFB = sbase + (uint32_t)((wm * 64 + r7 + ((mA & 1) << 3)) * ROW_STRIDE);
    const uint32_t bFB = sbase + B_REG_OFF + (uint32_t)((wn * 32 + r7 + ((mA >> 1) << 3)) * ROW_STRIDE);
    const uint32_t xA0 = (uint32_t)(gbA * 16), xA1 = xA0 + 32;
    const uint32_t xB0 = (uint32_t)(gbB * 16), xB1 = xB0 + 32;

    // ---- accumulators: 4 i-groups x 4 jn-groups x 4 ----
    float d[4][4][4];
    #pragma unroll
    for (int i = 0; i < 4; i++)
        #pragma unroll
        for (int j = 0; j < 4; j++)
            #pragma unroll
            for (int r = 0; r < 4; r++) d[i][j][r] = 0.0f;

    auto load_stage = [&](uint32_t bufoff) {
        cp16(a_dst0 + bufoff,                     a_run);
        cp16(a_dst0 + bufoff + 64 * ROW_STRIDE,   a_run + (size_t)64 * DIMK);
        cp16(b_dst0 + bufoff,                     b_run);
        cp16(b_dst0 + bufoff + 64 * ROW_STRIDE,   b_run + (size_t)64 * DIMK);
        a_run += BKH; b_run += BKH;
    };

    auto compute_chunk = [&](uint32_t ab, uint32_t bb, uint32_t xa, uint32_t xb) {
        uint32_t bf[2][4];
        #pragma unroll
        for (int jp = 0; jp < 2; jp++)
            ldsm_x4(bf[jp], bb + jp * (16 * ROW_STRIDE) + xb);
        #pragma unroll
        for (int ib = 0; ib < 4; ib++) {
            uint32_t af[4];
            ldsm_x4(af, ab + ib * (16 * ROW_STRIDE) + xa);
            #pragma unroll
            for (int jp = 0; jp < 2; jp++) {
                mma_f16(d[ib][2*jp],   af[0], af[1], af[2], af[3], bf[jp][0], bf[jp][1]);
                mma_f16(d[ib][2*jp+1], af[0], af[1], af[2], af[3], bf[jp][2], bf[jp][3]);
            }
        }
    };

    // preload stages 0,1
    load_stage(0); CP_COMMIT();
    load_stage(TILE_B); CP_COMMIT();

    int bufc = 0, bufl = 2;
    #pragma unroll 1
    for (int s = 0; s < NITER; s++) {
        CP_WAIT1();
        __syncthreads();
        if (s < NITER - 2) load_stage((uint32_t)(bufl * TILE_B));
        CP_COMMIT();
        const uint32_t ab = aFB + bufc * TILE_B;
        const uint32_t bb = bFB + bufc * TILE_B;
        compute_chunk(ab, bb, xA0, xB0);
        compute_chunk(ab, bb, xA1, xB1);
        bufc = (bufc == 2) ? 0 : bufc + 1;
        bufl = (bufl == 2) ? 0 : bufl + 1;
    }
    CP_WAIT0();

    // ---------------- epilogue ----------------
    if (is_att) {
        #pragma unroll
        for (int i = 0; i < 4; i++) {
            float m0 = -CUDART_INF_F, m1 = -CUDART_INF_F;
            #pragma unroll
            for (int jn = 0; jn < 4; jn++) {
                int nb = wn * 32 + jn * 8 + 2 * c;
                float bz0 = bias_s[nb], bz1 = bias_s[nb + 1];
                m0 = fmaxf(m0, fmaxf(d[i][jn][0] + bz0, d[i][jn][1] + bz1));
                m1 = fmaxf(m1, fmaxf(d[i][jn][2] + bz0, d[i][jn][3] + bz1));
            }
            m0 = fmaxf(m0, __shfl_xor_sync(0xffffffffu, m0, 1));
            m0 = fmaxf(m0, __shfl_xor_sync(0xffffffffu, m0, 2));
            m1 = fmaxf(m1, __shfl_xor_sync(0xffffffffu, m1, 1));
            m1 = fmaxf(m1, __shfl_xor_sync(0xffffffffu, m1, 2));
            if (c == 0) {
                redm[(wm * 64 + i * 16 + g) * 4 + wn]     = m0;
                redm[(wm * 64 + i * 16 + g + 8) * 4 + wn] = m1;
            }
        }
        if (fh) {
            float cs[4][2];
            #pragma unroll
            for (int jn = 0; jn < 4; jn++) { cs[jn][0] = 0.0f; cs[jn][1] = 0.0f; }
            #pragma unroll
            for (int i = 0; i < 4; i++) {
                float rf0 = rowfac_s[wm * 64 + i * 16 + g];
                float rf1 = rowfac_s[wm * 64 + i * 16 + g + 8];
                #pragma unroll
                for (int jn = 0; jn < 4; jn++) {
                    cs[jn][0] += d[i][jn][0] * rf0 + d[i][jn][2] * rf1;
                    cs[jn][1] += d[i][jn][1] * rf0 + d[i][jn][3] * rf1;
                }
            }
            #pragma unroll
            for (int jn = 0; jn < 4; jn++) {
                #pragma unroll
                for (int u = 0; u < 2; u++) {
                    float s = cs[jn][u];
                    s += __shfl_xor_sync(0xffffffffu, s, 4);
                    s += __shfl_xor_sync(0xffffffffu, s, 8);
                    s += __shfl_xor_sync(0xffffffffu, s, 16);
                    if (lane < 4) atomicAdd(&csum_s[wn * 32 + jn * 8 + 2 * c + u], s);
                }
            }
        }
        __syncthreads();
        if (tid < 128) {
            float m = fmaxf(fmaxf(redm[tid * 4 + 0], redm[tid * 4 + 1]),
                            fmaxf(redm[tid * 4 + 2], redm[tid * 4 + 3]));
            atomicMax(&g_rowmax[row0 + tid], enc_f(m));
        }
        if (fh && tid < 128) {
            int n = col0 + tid;
            if (n < NBLK) {
                int b = row0 >> 10;
                atomicAdd(&g_s[b * NBLK + n], csum_s[tid]);
            }
        }
    } else {
        float acc = 0.0f;
        #pragma unroll
        for (int i = 0; i < 4; i++) {
            int m0 = row0 + wm * 64 + i * 16 + g;
            #pragma unroll
            for (int jn = 0; jn < 4; jn++) {
                int n0 = col0 + wn * 32 + jn * 8 + 2 * c;
                float e;
                e = d[i][jn][0] - ((m0 == n0     && m0 < NBLK) ? 1.0f : 0.0f); acc += e * e;
                e = d[i][jn][1] - ((m0 == n0 + 1 && m0 < NBLK) ? 1.0f : 0.0f); acc += e * e;
                e = d[i][jn][2] - ((m0 + 8 == n0     && m0 + 8 < NBLK) ? 1.0f : 0.0f); acc += e * e;
                e = d[i][jn][3] - ((m0 + 8 == n0 + 1 && m0 + 8 < NBLK) ? 1.0f : 0.0f); acc += e * e;
            }
        }
        acc *= dupw;
        #pragma unroll
        for (int o = 16; o; o >>= 1) acc += __shfl_xor_sync(0xffffffffu, acc, o);
        if (lane == 0) csum_s[wid] = acc;
        __syncthreads();
        if (tid == 0) {
            float t = 0.0f;
            #pragma unroll
            for (int w = 0; w < 8; w++) t += csum_s[w];
            atomicAdd(&g_div, t);
        }
    }
}

// ---------------- finalize ----------------
template <typename Op>
__device__ __forceinline__ float block_reduce(float v, Op op, float ident, float* sbuf) {
    __syncthreads();
    int tid = threadIdx.x, lane = tid & 31, wid = tid >> 5;
    #pragma unroll
    for (int o = 16; o; o >>= 1) v = op(v, __shfl_down_sync(0xffffffffu, v, o));
    if (lane == 0) sbuf[wid] = v;
    __syncthreads();
    int nw = blockDim.x >> 5;
    if (wid == 0) {
        float w = (lane < nw) ? sbuf[lane] : ident;
        #pragma unroll
        for (int o = 16; o; o >>= 1) w = op(w, __shfl_down_sync(0xffffffffu, w, o));
        if (lane == 0) sbuf[0] = w;
    }
    __syncthreads();
    return sbuf[0];
}
struct OpSum { __device__ float operator()(float a, float b) const { return a + b; } };
struct OpMax { __device__ float operator()(float a, float b) const { return fmaxf(a, b); } };

__global__ void finalize_kernel(const int* __restrict__ mask, float* __restrict__ out) {
    __shared__ float sb_min[32];
    __shared__ float rbuf[32];
    __shared__ float smax[NB_HALF];
    __shared__ float sinvz[NB_HALF];

    int tid = threadIdx.x;
    int lane = tid & 31, wid = tid >> 5;

    {
        int b = wid;
        float mn = CUDART_INF_F;
        for (int t = lane; t < T_PER_B; t += 32) {
            int gr = b * T_PER_B + t;
            if (mask[gr] > 0) mn = fminf(mn, dec_f(g_rowmax[gr]));
        }
        #pragma unroll
        for (int o = 16; o; o >>= 1) mn = fminf(mn, __shfl_down_sync(0xffffffffu, mn, o));
        if (lane == 0) sb_min[b] = mn;
    }
    __syncthreads();

    for (int b = 0; b < NB_HALF; b++) {
        float mx = -CUDART_INF_F;
        for (int n = tid; n < NBLK; n += blockDim.x) mx = fmaxf(mx, g_s[b * NBLK + n]);
        mx = block_reduce(mx, OpMax(), -CUDART_INF_F, rbuf);
        if (tid == 0) smax[b] = mx;
        float se = 0.0f;
        for (int n = tid; n < NBLK; n += blockDim.x) se += expf(g_s[b * NBLK + n] - mx);
        se = block_reduce(se, OpSum(), 0.0f, rbuf);
        if (tid == 0) sinvz[b] = 1.0f / se;
        __syncthreads();
    }

    float usq = 0.0f;
    for (int n = tid; n < NBLK; n += blockDim.x) {
        float tmp = 0.0f;
        #pragma unroll
        for (int b = 0; b < NB_HALF; b++)
            tmp += expf(g_s[b * NBLK + n] - smax[b]) * sinvz[b];
        tmp *= (1.0f / (float)NB_HALF);
        usq += tmp * tmp;
    }
    usq = block_reduce(usq, OpSum(), 0.0f, rbuf);

    if (tid == 0) {
        float mean_min = 0.0f, mean_ab = 0.0f;
        for (int b = 0; b < NB_HALF; b++) { mean_min += sb_min[b]; mean_ab += sb_min[NB_HALF + b]; }
        mean_min *= (1.0f / (float)NB_HALF);
        mean_ab  *= (1.0f / (float)NB_HALF);
        out[0] = 0.2f * sqrtf(g_div);
        out[1] = 2.0f - mean_min + mean_ab;
        out[2] = 0.5f * sqrtf(usq);
    }
}

// ---------------- launch ----------------
extern "C" void kernel_launch(void* const* d_in, const int* in_sizes, int n_in,
                              void* d_out, int out_size) {
    const float* x = nullptr;
    const int*   mask = nullptr;
    const float* w = nullptr;
    for (int i = 0; i < n_in; i++) {
        if (in_sizes[i] == NROWS * DIMK)      x = (const float*)d_in[i];
        else if (in_sizes[i] == NROWS)        mask = (const int*)d_in[i];
        else if (in_sizes[i] == NBLK * DIMK)  w = (const float*)d_in[i];
    }
    float* out = (float*)d_out;

    cudaFuncSetAttribute(gemm_run, cudaFuncAttributeMaxDynamicSharedMemorySize, SMEM_BYTES);

    init_kernel<<<(NROWS + 255) / 256, 256>>>();
    conv_x_kernel<<<NROWS, 256>>>(x);
    conv_w_kernel<<<NPAD, 256>>>(w);
    gemm_run<<<N_ATT_CTAS + N_DIV_CTAS, NTH, SMEM_BYTES>>>(mask);
    finalize_kernel<<<1, 1024>>>(mask, out);
}